// round 11
// baseline (speedup 1.0000x reference)
#include <cuda_runtime.h>

// Problem constants: B=64, H=64, W=64, n=256, NF=513, L=63*63=3969, alpha^2=25

__device__ float g_state[64 * 64 * 64 * 256];   // [cell=(i*64+j)][b][n]
__device__ float g_A[64 * 513 * 520];           // augmented [513 x 514] per batch, ld=520

// ---- packed f32x2 helpers (dual fp32 pipe) ---------------------------------
__device__ __forceinline__ unsigned long long pk2(float a, float b) {
    unsigned long long r;
    asm("mov.b64 %0,{%1,%2};" : "=l"(r) : "f"(a), "f"(b));
    return r;
}
__device__ __forceinline__ void fma2(unsigned long long& d,
                                     unsigned long long a, unsigned long long b) {
    asm("fma.rn.f32x2 %0,%1,%2,%0;" : "+l"(d) : "l"(a), "l"(b));
}
__device__ __forceinline__ void unpk2(unsigned long long v, float& a, float& b) {
    asm("mov.b64 {%0,%1},%2;" : "=f"(a), "=f"(b) : "l"(v));
}

// ---------------------------------------------------------------------------
// Phase 1: wavefront scan, one launch per anti-diagonal.  VERBATIM from the
// best passing build (R2, 9168us): 32 batches x 128 features per block,
// grid (cells, 2, 2), k-chunk 32, double-buffered smem, f32x2 over batch.
// ---------------------------------------------------------------------------
__global__ __launch_bounds__(256) void scan_diag(
    const float* __restrict__ x, const float* __restrict__ Win,
    const float* __restrict__ W1, const float* __restrict__ W2,
    int d, int i_min)
{
    __shared__ __align__(16) float in_s[2][32][34];   // [buf][k][b] (pad 34)
    __shared__ __align__(16) float w_s[2][32][128];   // [buf][k][n]

    const int i = i_min + (int)blockIdx.x;
    const int j = d - i;
    const int b0 = (int)blockIdx.y * 32;
    const int n0 = (int)blockIdx.z * 128;
    const int tid = (int)threadIdx.x;
    const int tx = tid & 31;    // n: 4 cols
    const int ty = tid >> 5;    // b: 4 rows (2 pairs)

    const bool hasL = (j > 0);
    const bool hasU = (i > 0);
    const int cellL = hasL ? ((i * 64 + (j - 1)) * 64) : 0;
    const int cellU = hasU ? (((i - 1) * 64 + j) * 64) : 0;

    const int bb = tid >> 3;   // 0..31 batch for input staging
    const int kq = tid & 7;    // 0..7  k-quad for input staging

    unsigned long long acc[2][4];
#pragma unroll
    for (int p = 0; p < 2; ++p)
#pragma unroll
        for (int c = 0; c < 4; ++c) acc[p][c] = 0ull;

    float4 inr;
    float4 wr[4];

    auto LOADC = [&](int kc) {
        const int k0 = kc * 32;
        const bool isLeft = (k0 < 256);
        const bool has = isLeft ? hasL : hasU;
        const int ks = isLeft ? k0 : (k0 - 256);
        inr = make_float4(0.f, 0.f, 0.f, 0.f);
        if (has) {
            const int cell = isLeft ? cellL : cellU;
            inr = *(const float4*)&g_state[(cell + b0 + bb) * 256 + ks + kq * 4];
        }
        const float* __restrict__ Wm = isLeft ? W1 : W2;
#pragma unroll
        for (int t = 0; t < 4; ++t) {
            int fi = tid + t * 256;
            int kl = fi >> 5;
            int cq = fi & 31;
            wr[t] = *(const float4*)&Wm[(ks + kl) * 256 + n0 + cq * 4];
        }
    };
    auto STOREC = [&](int buf) {
        in_s[buf][kq * 4 + 0][bb] = inr.x;
        in_s[buf][kq * 4 + 1][bb] = inr.y;
        in_s[buf][kq * 4 + 2][bb] = inr.z;
        in_s[buf][kq * 4 + 3][bb] = inr.w;
#pragma unroll
        for (int t = 0; t < 4; ++t) {
            int fi = tid + t * 256;
            int kl = fi >> 5;
            int cq = fi & 31;
            *(float4*)&w_s[buf][kl][cq * 4] = wr[t];
        }
    };

    LOADC(0);
    STOREC(0);

    for (int kc = 0; kc < 16; ++kc) {
        __syncthreads();
        if (kc < 15) LOADC(kc + 1);
        const int buf = kc & 1;
#pragma unroll 8
        for (int kl = 0; kl < 32; ++kl) {
            unsigned long long a01 = *(const unsigned long long*)&in_s[buf][kl][ty * 4];
            unsigned long long a23 = *(const unsigned long long*)&in_s[buf][kl][ty * 4 + 2];
            float4 w = *(const float4*)&w_s[buf][kl][tx * 4];
            unsigned long long wx = pk2(w.x, w.x);
            unsigned long long wy = pk2(w.y, w.y);
            unsigned long long wz = pk2(w.z, w.z);
            unsigned long long ww = pk2(w.w, w.w);
            fma2(acc[0][0], a01, wx); fma2(acc[0][1], a01, wy);
            fma2(acc[0][2], a01, wz); fma2(acc[0][3], a01, ww);
            fma2(acc[1][0], a23, wx); fma2(acc[1][1], a23, wy);
            fma2(acc[1][2], a23, wz); fma2(acc[1][3], a23, ww);
        }
        if (kc < 15) STOREC((kc + 1) & 1);
    }

    // epilogue: + x*Win, tanh, store
    const int cell = (i * 64 + j) * 64;
    float4 wv = *(const float4*)&Win[n0 + tx * 4];
#pragma unroll
    for (int p = 0; p < 2; ++p) {
        float lo0, hi0, lo1, hi1, lo2, hi2, lo3, hi3;
        unpk2(acc[p][0], lo0, hi0);
        unpk2(acc[p][1], lo1, hi1);
        unpk2(acc[p][2], lo2, hi2);
        unpk2(acc[p][3], lo3, hi3);
        const int bA = b0 + ty * 4 + 2 * p;
        const int bB = bA + 1;
        const float xA = x[(bA * 64 + i) * 64 + j];
        const float xB = x[(bB * 64 + i) * 64 + j];
        float4 oA, oB;
        oA.x = tanhf(lo0 + xA * wv.x); oA.y = tanhf(lo1 + xA * wv.y);
        oA.z = tanhf(lo2 + xA * wv.z); oA.w = tanhf(lo3 + xA * wv.w);
        oB.x = tanhf(hi0 + xB * wv.x); oB.y = tanhf(hi1 + xB * wv.y);
        oB.z = tanhf(hi2 + xB * wv.z); oB.w = tanhf(hi3 + xB * wv.w);
        *(float4*)&g_state[(cell + bA) * 256 + n0 + tx * 4] = oA;
        *(float4*)&g_state[(cell + bB) * 256 + n0 + tx * 4] = oB;
    }
}

// ---------------------------------------------------------------------------
// Phase 2a: HtH with 128x128 tiles over 4 column-groups (10 pairs) -> halves
// the g_state re-read traffic vs 64-wide tiles.  Diagonal pairs stage ONE
// group.  Rows/cols 0..511 only; row/col 512 handled in htu_kernel.
// Per-output l-order: chunks of 32, kk ascending -> values bitwise == before.
// ---------------------------------------------------------------------------
__global__ __launch_bounds__(256) void hth_kernel()
{
    __shared__ __align__(16) float Hd[32][128];
    __shared__ __align__(16) float He[32][128];

    // pair (ti, tj), ti <= tj, over 4 groups of 128 cols: 10 pairs
    int rem = (int)blockIdx.x;
    int ti = 0;
    while (rem >= 4 - ti) { rem -= 4 - ti; ++ti; }
    const int tj = ti + rem;
    const int b = (int)blockIdx.y;
    const int d0 = ti * 128, e0 = tj * 128;
    const bool dLeft = d0 < 256;
    const bool eLeft = e0 < 256;
    const int dColn = dLeft ? d0 : d0 - 256;
    const int eColn = eLeft ? e0 : e0 - 256;
    const bool diag = (ti == tj);

    const int tid = (int)threadIdx.x;
    const int tx = tid & 15, ty = tid >> 4;    // 8 cols at tx*8, 8 rows at ty*8
    const int dd = tid & 127, kb = tid >> 7;   // staging col / k-phase

    int rs[16], cs[16];
#pragma unroll
    for (int t = 0; t < 16; ++t) { rs[t] = 0; cs[t] = kb + t * 2; }

    unsigned long long acc[4][8];
#pragma unroll
    for (int rp = 0; rp < 4; ++rp)
#pragma unroll
        for (int c = 0; c < 8; ++c) acc[rp][c] = 0ull;

    for (int l0 = 0; l0 < 3969; l0 += 32) {
        __syncthreads();
#pragma unroll
        for (int t = 0; t < 16; ++t) {
            const int kk = kb + t * 2;
            const int r = rs[t], c = cs[t];
            const bool valid = (r < 63);
            {
                int cellD = dLeft ? ((r + 1) * 64 + c) : (r * 64 + c + 1);
                Hd[kk][dd] = valid ?
                    g_state[(cellD * 64 + b) * 256 + dColn + dd] : 0.f;
            }
            if (!diag) {
                int cellE = eLeft ? ((r + 1) * 64 + c) : (r * 64 + c + 1);
                He[kk][dd] = valid ?
                    g_state[(cellE * 64 + b) * 256 + eColn + dd] : 0.f;
            }
            int cn = c + 32, rn = r;
            if (cn >= 63) { cn -= 63; ++rn; }
            rs[t] = rn; cs[t] = cn;
        }
        __syncthreads();

        const float (*Hep)[128] = diag ? Hd : He;
#pragma unroll 4
        for (int kk = 0; kk < 32; ++kk) {
            unsigned long long a[4];
#pragma unroll
            for (int rp = 0; rp < 4; ++rp)
                a[rp] = *(const unsigned long long*)&Hd[kk][ty * 8 + rp * 2];
            float4 w0 = *(const float4*)&Hep[kk][tx * 8];
            float4 w1 = *(const float4*)&Hep[kk][tx * 8 + 4];
            unsigned long long wp[8];
            wp[0] = pk2(w0.x, w0.x); wp[1] = pk2(w0.y, w0.y);
            wp[2] = pk2(w0.z, w0.z); wp[3] = pk2(w0.w, w0.w);
            wp[4] = pk2(w1.x, w1.x); wp[5] = pk2(w1.y, w1.y);
            wp[6] = pk2(w1.z, w1.z); wp[7] = pk2(w1.w, w1.w);
#pragma unroll
            for (int rp = 0; rp < 4; ++rp)
#pragma unroll
                for (int c = 0; c < 8; ++c)
                    fma2(acc[rp][c], a[rp], wp[c]);
        }
    }

    float* __restrict__ A = g_A + b * 513 * 520;
#pragma unroll
    for (int rp = 0; rp < 4; ++rp) {
        const int dr0 = d0 + ty * 8 + rp * 2;
#pragma unroll
        for (int c = 0; c < 8; ++c) {
            const int e = e0 + tx * 8 + c;
            float va, vb;
            unpk2(acc[rp][c], va, vb);
            if (dr0 == e) va += 25.0f;
            if (dr0 + 1 == e) vb += 25.0f;
            A[dr0 * 520 + e] = va;
            A[(dr0 + 1) * 520 + e] = vb;
            if (!diag) {
                A[e * 520 + dr0] = va;
                A[e * 520 + dr0 + 1] = vb;
            }
        }
    }
}

// ---------------------------------------------------------------------------
// Phase 2b: HtU (RHS col 513) AND ones row/col 512, fused in one pass over
// the same loads.  EXACT sequential (r,c) numerics per accumulator — do NOT
// reassociate (R4 lesson: the solve amplifies perturbations).
// fma(1,h,acc) == acc+h bitwise, so acc1 += h matches the old tile path.
// ---------------------------------------------------------------------------
__global__ __launch_bounds__(256) void htu_kernel(const float* __restrict__ x)
{
    const int b = (int)blockIdx.x;
    const int dcol = (int)blockIdx.y * 256 + (int)threadIdx.x;
    if (dcol > 512) return;
    const float* __restrict__ xb = x + b * 4096;
    float* __restrict__ A = g_A + b * 513 * 520;

    if (dcol < 512) {
        const bool left = (dcol < 256);
        const int d2 = left ? dcol : dcol - 256;
        float acct = 0.f;   // sum target * H[l][dcol]
        float acc1 = 0.f;   // sum H[l][dcol]  (ones row/col)
        for (int r = 0; r < 63; ++r)
            for (int c = 0; c < 63; ++c) {
                int cellb = left ? ((r + 1) * 64 + c) : (r * 64 + c + 1);
                float h = g_state[(cellb * 64 + b) * 256 + d2];
                acct += xb[(r + 1) * 64 + c + 1] * h;
                acc1 += h;
            }
        A[dcol * 520 + 513] = acct;          // RHS
        A[512 * 520 + dcol] = acc1;          // ones row
        A[dcol * 520 + 512] = acc1;          // ones col
    } else {
        float acct = 0.f;
        for (int r = 0; r < 63; ++r)
            for (int c = 0; c < 63; ++c)
                acct += xb[(r + 1) * 64 + c + 1];
        A[512 * 520 + 513] = acct;           // RHS last entry
        A[512 * 520 + 512] = 3969.0f + 25.0f;  // L + alpha^2 (exact)
    }
}

// ---------------------------------------------------------------------------
// Phase 3: per-batch blocked LU (no pivoting; SPD) + back substitution.
// (verbatim from passing build)
// ---------------------------------------------------------------------------
__global__ __launch_bounds__(512) void solve_kernel(float* __restrict__ out)
{
    __shared__ float P[513 * 17];
    __shared__ __align__(16) float Us[16 * 132];
    __shared__ float red[16];

    const int b = (int)blockIdx.x;
    const int tid = (int)threadIdx.x;
    float* __restrict__ A = g_A + b * 513 * 520;

    for (int k0 = 0; k0 < 513; k0 += 16) {
        const int nb = (513 - k0) < 16 ? (513 - k0) : 16;
        const int nrows = 513 - k0;

        for (int idx = tid; idx < nrows * nb; idx += 512) {
            int rr = idx / nb, cc = idx - rr * nb;
            P[rr * 17 + cc] = A[(k0 + rr) * 520 + (k0 + cc)];
        }
        __syncthreads();

        for (int kk = 0; kk < nb; ++kk) {
            float inv = 1.0f / P[kk * 17 + kk];
            for (int rr = kk + 1 + tid; rr < nrows; rr += 512) {
                float lv = P[rr * 17 + kk] * inv;
                P[rr * 17 + kk] = lv;
                for (int cc = kk + 1; cc < nb; ++cc)
                    P[rr * 17 + cc] -= lv * P[kk * 17 + cc];
            }
            __syncthreads();
        }

        for (int idx = tid; idx < nrows * nb; idx += 512) {
            int rr = idx / nb, cc = idx - rr * nb;
            A[(k0 + rr) * 520 + (k0 + cc)] = P[rr * 17 + cc];
        }
        __syncthreads();

        const int cstart = k0 + nb;
        const int width = 514 - cstart;
        for (int ch = 0; ch < width; ch += 128) {
            int wlen = width - ch; if (wlen > 128) wlen = 128;
            const int wlenp = (wlen + 3) & ~3;
            const int cbase = cstart + ch;

            for (int idx = tid; idx < nb * wlenp; idx += 512) {
                int rr = idx / wlenp, cc = idx - rr * wlenp;
                Us[rr * 132 + cc] = A[(k0 + rr) * 520 + cbase + cc];
            }
            __syncthreads();

            for (int cc = tid; cc < wlenp; cc += 512) {
                float col[16];
                for (int m = 0; m < nb; ++m) col[m] = Us[m * 132 + cc];
                for (int kk = 1; kk < nb; ++kk) {
                    float v = col[kk];
                    for (int m = 0; m < kk; ++m) v -= P[kk * 17 + m] * col[m];
                    col[kk] = v;
                }
                for (int m = 0; m < nb; ++m) {
                    Us[m * 132 + cc] = col[m];
                    A[(k0 + m) * 520 + cbase + cc] = col[m];
                }
            }
            __syncthreads();

            const int trows = nrows - nb;
            const int npr = (trows + 1) >> 1;
            const int ncq = wlenp >> 2;
            for (int idx = tid; idx < npr * ncq; idx += 512) {
                int pr = idx / ncq, cq = idx - pr * ncq;
                int row0 = cstart + pr * 2;
                int cc = cq * 4;
                bool has2 = (pr * 2 + 1) < trows;
                const unsigned long long* pa0 =
                    (const unsigned long long*)&A[row0 * 520 + cbase + cc];
                const unsigned long long* pa1 =
                    (const unsigned long long*)&A[(row0 + 1) * 520 + cbase + cc];
                unsigned long long a00 = pa0[0], a01v = pa0[1];
                unsigned long long a10 = has2 ? pa1[0] : a00;
                unsigned long long a11 = has2 ? pa1[1] : a01v;
                const float* P0 = &P[(row0 - k0) * 17];
                const float* P1 = has2 ? (P0 + 17) : P0;
#pragma unroll
                for (int m = 0; m < 16; ++m) {
                    if (m < nb) {
                        const unsigned long long* pu =
                            (const unsigned long long*)&Us[m * 132 + cc];
                        unsigned long long u01 = pu[0], u23 = pu[1];
                        float p0 = P0[m], p1 = P1[m];
                        unsigned long long np0 = pk2(-p0, -p0);
                        unsigned long long np1 = pk2(-p1, -p1);
                        fma2(a00, u01, np0); fma2(a01v, u23, np0);
                        fma2(a10, u01, np1); fma2(a11, u23, np1);
                    }
                }
                unsigned long long* sa0 =
                    (unsigned long long*)&A[row0 * 520 + cbase + cc];
                sa0[0] = a00; sa0[1] = a01v;
                if (has2) {
                    unsigned long long* sa1 =
                        (unsigned long long*)&A[(row0 + 1) * 520 + cbase + cc];
                    sa1[0] = a10; sa1[1] = a11;
                }
            }
            __syncthreads();
        }
    }

    float* xs = P;
    const int lane = tid & 31, wid = tid >> 5;
    for (int r = 512; r >= 0; --r) {
        float part = 0.f;
        for (int c = r + 1 + tid; c <= 512; c += 512)
            part += A[r * 520 + c] * xs[c];
#pragma unroll
        for (int off = 16; off > 0; off >>= 1)
            part += __shfl_down_sync(0xffffffffu, part, off);
        if (lane == 0) red[wid] = part;
        __syncthreads();
        if (tid == 0) {
            float s = 0.f;
#pragma unroll
            for (int w2 = 0; w2 < 16; ++w2) s += red[w2];
            xs[r] = (A[r * 520 + 513] - s) / A[r * 520 + r];
        }
        __syncthreads();
    }
    for (int i2 = tid; i2 < 513; i2 += 512)
        out[b * 513 + i2] = xs[i2];
}

// ---------------------------------------------------------------------------
extern "C" void kernel_launch(void* const* d_in, const int* in_sizes, int n_in,
                              void* d_out, int out_size)
{
    const float* x   = (const float*)d_in[0];
    const float* Win = (const float*)d_in[1];
    const float* W1  = (const float*)d_in[2];
    const float* W2  = (const float*)d_in[3];
    float* out = (float*)d_out;

    for (int d = 0; d < 127; ++d) {
        int i_min = d > 63 ? d - 63 : 0;
        int i_max = d < 63 ? d : 63;
        dim3 grid(i_max - i_min + 1, 2, 2);
        scan_diag<<<grid, 256>>>(x, Win, W1, W2, d, i_min);
    }
    hth_kernel<<<dim3(10, 64), 256>>>();
    htu_kernel<<<dim3(64, 3), 256>>>(x);
    solve_kernel<<<64, 512>>>(out);
}

// round 12
// speedup vs baseline: 1.1540x; 1.1540x over previous
#include <cuda_runtime.h>

// Problem constants: B=64, H=64, W=64, n=256, NF=513, L=63*63=3969, alpha^2=25

__device__ float g_state[64 * 64 * 64 * 256];   // [cell=(i*64+j)][b][n]
__device__ float g_A[64 * 513 * 520];           // augmented [513 x 514] per batch, ld=520

// ---- packed f32x2 helpers (dual fp32 pipe) ---------------------------------
__device__ __forceinline__ unsigned long long pk2(float a, float b) {
    unsigned long long r;
    asm("mov.b64 %0,{%1,%2};" : "=l"(r) : "f"(a), "f"(b));
    return r;
}
__device__ __forceinline__ void fma2(unsigned long long& d,
                                     unsigned long long a, unsigned long long b) {
    asm("fma.rn.f32x2 %0,%1,%2,%0;" : "+l"(d) : "l"(a), "l"(b));
}
__device__ __forceinline__ void unpk2(unsigned long long v, float& a, float& b) {
    asm("mov.b64 {%0,%1},%2;" : "=f"(a), "=f"(b) : "l"(v));
}

// ---------------------------------------------------------------------------
// Phase 1: wavefront scan, one launch per anti-diagonal.  R2 tiling
// (32 batches x 128 features per block, grid (cells,2,2), k-chunk 32) with
// PREFETCH DEPTH 2: triple-buffered smem + two register staging sets, so
// each chunk's LDGs get a full chunk of latency headroom before STOREC.
// Inner-loop math and per-output k order (0..511 ascending) are unchanged
// -> states bitwise identical to the 9168us build.
// ---------------------------------------------------------------------------
#define IN_BUF  (32 * 34)
#define W_BUF   (32 * 128)
#define SCAN_SMEM (3 * (IN_BUF + W_BUF) * 4)     // 61440 bytes

__global__ __launch_bounds__(256) void scan_diag(
    const float* __restrict__ x, const float* __restrict__ Win,
    const float* __restrict__ W1, const float* __restrict__ W2,
    int d, int i_min)
{
    extern __shared__ float sm[];
    float* in_base = sm;                    // [3][32][34]
    float* w_base  = sm + 3 * IN_BUF;       // [3][32][128]

    const int i = i_min + (int)blockIdx.x;
    const int j = d - i;
    const int b0 = (int)blockIdx.y * 32;
    const int n0 = (int)blockIdx.z * 128;
    const int tid = (int)threadIdx.x;
    const int tx = tid & 31;    // n: 4 cols
    const int ty = tid >> 5;    // b: 4 rows (2 pairs)

    const bool hasL = (j > 0);
    const bool hasU = (i > 0);
    const int cellL = hasL ? ((i * 64 + (j - 1)) * 64) : 0;
    const int cellU = hasU ? (((i - 1) * 64 + j) * 64) : 0;

    const int bb = tid >> 3;   // 0..31 batch for input staging
    const int kq = tid & 7;    // 0..7  k-quad for input staging

    unsigned long long acc[2][4];
#pragma unroll
    for (int p = 0; p < 2; ++p)
#pragma unroll
        for (int c = 0; c < 4; ++c) acc[p][c] = 0ull;

    float4 inr[2];
    float4 wr[2][4];

    auto LOADC = [&](int kc, int s) {
        const int k0 = kc * 32;
        const bool isLeft = (k0 < 256);
        const bool has = isLeft ? hasL : hasU;
        const int ks = isLeft ? k0 : (k0 - 256);
        inr[s] = make_float4(0.f, 0.f, 0.f, 0.f);
        if (has) {
            const int cell = isLeft ? cellL : cellU;
            inr[s] = *(const float4*)&g_state[(cell + b0 + bb) * 256 + ks + kq * 4];
        }
        const float* __restrict__ Wm = isLeft ? W1 : W2;
#pragma unroll
        for (int t = 0; t < 4; ++t) {
            int fi = tid + t * 256;
            int kl = fi >> 5;
            int cq = fi & 31;
            wr[s][t] = *(const float4*)&Wm[(ks + kl) * 256 + n0 + cq * 4];
        }
    };
    auto STOREC = [&](int s, int buf) {
        float* ip = in_base + buf * IN_BUF;
        ip[(kq * 4 + 0) * 34 + bb] = inr[s].x;
        ip[(kq * 4 + 1) * 34 + bb] = inr[s].y;
        ip[(kq * 4 + 2) * 34 + bb] = inr[s].z;
        ip[(kq * 4 + 3) * 34 + bb] = inr[s].w;
        float* wp = w_base + buf * W_BUF;
#pragma unroll
        for (int t = 0; t < 4; ++t) {
            int fi = tid + t * 256;
            int kl = fi >> 5;
            int cq = fi & 31;
            *(float4*)&wp[kl * 128 + cq * 4] = wr[s][t];
        }
    };

    // prologue: buf0 stored, chunk1 in-flight in register set 1
    LOADC(0, 0);
    STOREC(0, 0);
    LOADC(1, 1);

    for (int kc = 0; kc < 16; ++kc) {
        __syncthreads();
        // store chunk kc+1 (loaded one iteration ago -> LDGs have aged a full
        // chunk), then issue loads for chunk kc+2 into the freed set.
        if (kc < 15) STOREC((kc + 1) & 1, (kc + 1) % 3);
        if (kc < 14) LOADC(kc + 2, kc & 1);

        const float* ib = in_base + (kc % 3) * IN_BUF;
        const float* wb = w_base + (kc % 3) * W_BUF;
#pragma unroll 8
        for (int kl = 0; kl < 32; ++kl) {
            unsigned long long a01 = *(const unsigned long long*)&ib[kl * 34 + ty * 4];
            unsigned long long a23 = *(const unsigned long long*)&ib[kl * 34 + ty * 4 + 2];
            float4 w = *(const float4*)&wb[kl * 128 + tx * 4];
            unsigned long long wx = pk2(w.x, w.x);
            unsigned long long wy = pk2(w.y, w.y);
            unsigned long long wz = pk2(w.z, w.z);
            unsigned long long ww = pk2(w.w, w.w);
            fma2(acc[0][0], a01, wx); fma2(acc[0][1], a01, wy);
            fma2(acc[0][2], a01, wz); fma2(acc[0][3], a01, ww);
            fma2(acc[1][0], a23, wx); fma2(acc[1][1], a23, wy);
            fma2(acc[1][2], a23, wz); fma2(acc[1][3], a23, ww);
        }
    }

    // epilogue: + x*Win, tanh, store
    const int cell = (i * 64 + j) * 64;
    float4 wv = *(const float4*)&Win[n0 + tx * 4];
#pragma unroll
    for (int p = 0; p < 2; ++p) {
        float lo0, hi0, lo1, hi1, lo2, hi2, lo3, hi3;
        unpk2(acc[p][0], lo0, hi0);
        unpk2(acc[p][1], lo1, hi1);
        unpk2(acc[p][2], lo2, hi2);
        unpk2(acc[p][3], lo3, hi3);
        const int bA = b0 + ty * 4 + 2 * p;
        const int bB = bA + 1;
        const float xA = x[(bA * 64 + i) * 64 + j];
        const float xB = x[(bB * 64 + i) * 64 + j];
        float4 oA, oB;
        oA.x = tanhf(lo0 + xA * wv.x); oA.y = tanhf(lo1 + xA * wv.y);
        oA.z = tanhf(lo2 + xA * wv.z); oA.w = tanhf(lo3 + xA * wv.w);
        oB.x = tanhf(hi0 + xB * wv.x); oB.y = tanhf(hi1 + xB * wv.y);
        oB.z = tanhf(hi2 + xB * wv.z); oB.w = tanhf(hi3 + xB * wv.w);
        *(float4*)&g_state[(cell + bA) * 256 + n0 + tx * 4] = oA;
        *(float4*)&g_state[(cell + bB) * 256 + n0 + tx * 4] = oB;
    }
}

// ---------------------------------------------------------------------------
// Phase 2a: HtH = 64x64 tiles, both triangles, += 25 on diagonal.
// VERBATIM from the 9168us build.
// ---------------------------------------------------------------------------
__device__ __forceinline__ float loadH(int b, int l, int col) {
    if (l >= 3969) return 0.f;
    int r = l / 63;
    int c = l - r * 63;
    if (col < 256)
        return g_state[(((r + 1) * 64 + c) * 64 + b) * 256 + col];
    else if (col < 512)
        return g_state[((r * 64 + (c + 1)) * 64 + b) * 256 + (col - 256)];
    else
        return (col == 512) ? 1.f : 0.f;
}

__global__ __launch_bounds__(256) void hth_kernel()
{
    __shared__ __align__(16) float Hd[32][64];
    __shared__ __align__(16) float He[32][64];

    int rem = (int)blockIdx.x;
    int ti = 0;
    while (rem >= 9 - ti) { rem -= 9 - ti; ++ti; }
    const int tj = ti + rem;
    const int b = (int)blockIdx.y;
    const int d0 = ti * 64, e0 = tj * 64;

    const int tid = (int)threadIdx.x;
    const int tx = tid & 15, ty = tid >> 4;
    const int dd = tid & 63, kb = tid >> 6;

    unsigned long long acc[2][4];
#pragma unroll
    for (int p = 0; p < 2; ++p)
#pragma unroll
        for (int c = 0; c < 4; ++c) acc[p][c] = 0ull;

    for (int l0 = 0; l0 < 3969; l0 += 32) {
        __syncthreads();
#pragma unroll
        for (int t = 0; t < 8; ++t) {
            int kk = kb + t * 4;
            int l = l0 + kk;
            Hd[kk][dd] = loadH(b, l, d0 + dd);
            He[kk][dd] = loadH(b, l, e0 + dd);
        }
        __syncthreads();
#pragma unroll 8
        for (int kk = 0; kk < 32; ++kk) {
            unsigned long long a01 = *(const unsigned long long*)&Hd[kk][ty * 4];
            unsigned long long a23 = *(const unsigned long long*)&Hd[kk][ty * 4 + 2];
            float4 w = *(const float4*)&He[kk][tx * 4];
            unsigned long long wx = pk2(w.x, w.x);
            unsigned long long wy = pk2(w.y, w.y);
            unsigned long long wz = pk2(w.z, w.z);
            unsigned long long ww = pk2(w.w, w.w);
            fma2(acc[0][0], a01, wx); fma2(acc[0][1], a01, wy);
            fma2(acc[0][2], a01, wz); fma2(acc[0][3], a01, ww);
            fma2(acc[1][0], a23, wx); fma2(acc[1][1], a23, wy);
            fma2(acc[1][2], a23, wz); fma2(acc[1][3], a23, ww);
        }
    }

    float v[4][4];
#pragma unroll
    for (int p = 0; p < 2; ++p)
#pragma unroll
        for (int c = 0; c < 4; ++c)
            unpk2(acc[p][c], v[2 * p][c], v[2 * p + 1][c]);

    float* __restrict__ A = g_A + b * 513 * 520;
#pragma unroll
    for (int r = 0; r < 4; ++r) {
        int dr = d0 + ty * 4 + r;
        if (dr >= 513) continue;
#pragma unroll
        for (int c = 0; c < 4; ++c) {
            int e = e0 + tx * 4 + c;
            if (e >= 513) continue;
            float val = v[r][c];
            if (dr == e) val += 25.0f;
            A[dr * 520 + e] = val;
            if (ti != tj) A[e * 520 + dr] = val;
        }
    }
}

// ---------------------------------------------------------------------------
// Phase 2b: HtU -> column 513 of A.  EXACT sequential (r,c) numerics — do NOT
// reassociate (R4 lesson: the solve amplifies RHS perturbations).
// VERBATIM from the 9168us build.
// ---------------------------------------------------------------------------
__global__ __launch_bounds__(256) void htu_kernel(const float* __restrict__ x)
{
    const int b = (int)blockIdx.x;
    const int dcol = (int)blockIdx.y * 256 + (int)threadIdx.x;
    if (dcol >= 513) return;
    const float* __restrict__ xb = x + b * 4096;
    float acc = 0.f;
    if (dcol < 256) {
        for (int r = 0; r < 63; ++r)
            for (int c = 0; c < 63; ++c)
                acc += xb[(r + 1) * 64 + c + 1] *
                       g_state[(((r + 1) * 64 + c) * 64 + b) * 256 + dcol];
    } else if (dcol < 512) {
        const int d2 = dcol - 256;
        for (int r = 0; r < 63; ++r)
            for (int c = 0; c < 63; ++c)
                acc += xb[(r + 1) * 64 + c + 1] *
                       g_state[((r * 64 + (c + 1)) * 64 + b) * 256 + d2];
    } else {
        for (int r = 0; r < 63; ++r)
            for (int c = 0; c < 63; ++c)
                acc += xb[(r + 1) * 64 + c + 1];
    }
    g_A[(b * 513 + dcol) * 520 + 513] = acc;
}

// ---------------------------------------------------------------------------
// Phase 3: per-batch blocked LU (no pivoting; SPD) + back substitution.
// VERBATIM from the 9168us build.
// ---------------------------------------------------------------------------
__global__ __launch_bounds__(512) void solve_kernel(float* __restrict__ out)
{
    __shared__ float P[513 * 17];
    __shared__ __align__(16) float Us[16 * 132];
    __shared__ float red[16];

    const int b = (int)blockIdx.x;
    const int tid = (int)threadIdx.x;
    float* __restrict__ A = g_A + b * 513 * 520;

    for (int k0 = 0; k0 < 513; k0 += 16) {
        const int nb = (513 - k0) < 16 ? (513 - k0) : 16;
        const int nrows = 513 - k0;

        for (int idx = tid; idx < nrows * nb; idx += 512) {
            int rr = idx / nb, cc = idx - rr * nb;
            P[rr * 17 + cc] = A[(k0 + rr) * 520 + (k0 + cc)];
        }
        __syncthreads();

        for (int kk = 0; kk < nb; ++kk) {
            float inv = 1.0f / P[kk * 17 + kk];
            for (int rr = kk + 1 + tid; rr < nrows; rr += 512) {
                float lv = P[rr * 17 + kk] * inv;
                P[rr * 17 + kk] = lv;
                for (int cc = kk + 1; cc < nb; ++cc)
                    P[rr * 17 + cc] -= lv * P[kk * 17 + cc];
            }
            __syncthreads();
        }

        for (int idx = tid; idx < nrows * nb; idx += 512) {
            int rr = idx / nb, cc = idx - rr * nb;
            A[(k0 + rr) * 520 + (k0 + cc)] = P[rr * 17 + cc];
        }
        __syncthreads();

        const int cstart = k0 + nb;
        const int width = 514 - cstart;
        for (int ch = 0; ch < width; ch += 128) {
            int wlen = width - ch; if (wlen > 128) wlen = 128;
            const int wlenp = (wlen + 3) & ~3;
            const int cbase = cstart + ch;

            for (int idx = tid; idx < nb * wlenp; idx += 512) {
                int rr = idx / wlenp, cc = idx - rr * wlenp;
                Us[rr * 132 + cc] = A[(k0 + rr) * 520 + cbase + cc];
            }
            __syncthreads();

            for (int cc = tid; cc < wlenp; cc += 512) {
                float col[16];
                for (int m = 0; m < nb; ++m) col[m] = Us[m * 132 + cc];
                for (int kk = 1; kk < nb; ++kk) {
                    float v = col[kk];
                    for (int m = 0; m < kk; ++m) v -= P[kk * 17 + m] * col[m];
                    col[kk] = v;
                }
                for (int m = 0; m < nb; ++m) {
                    Us[m * 132 + cc] = col[m];
                    A[(k0 + m) * 520 + cbase + cc] = col[m];
                }
            }
            __syncthreads();

            const int trows = nrows - nb;
            const int npr = (trows + 1) >> 1;
            const int ncq = wlenp >> 2;
            for (int idx = tid; idx < npr * ncq; idx += 512) {
                int pr = idx / ncq, cq = idx - pr * ncq;
                int row0 = cstart + pr * 2;
                int cc = cq * 4;
                bool has2 = (pr * 2 + 1) < trows;
                const unsigned long long* pa0 =
                    (const unsigned long long*)&A[row0 * 520 + cbase + cc];
                const unsigned long long* pa1 =
                    (const unsigned long long*)&A[(row0 + 1) * 520 + cbase + cc];
                unsigned long long a00 = pa0[0], a01v = pa0[1];
                unsigned long long a10 = has2 ? pa1[0] : a00;
                unsigned long long a11 = has2 ? pa1[1] : a01v;
                const float* P0 = &P[(row0 - k0) * 17];
                const float* P1 = has2 ? (P0 + 17) : P0;
#pragma unroll
                for (int m = 0; m < 16; ++m) {
                    if (m < nb) {
                        const unsigned long long* pu =
                            (const unsigned long long*)&Us[m * 132 + cc];
                        unsigned long long u01 = pu[0], u23 = pu[1];
                        float p0 = P0[m], p1 = P1[m];
                        unsigned long long np0 = pk2(-p0, -p0);
                        unsigned long long np1 = pk2(-p1, -p1);
                        fma2(a00, u01, np0); fma2(a01v, u23, np0);
                        fma2(a10, u01, np1); fma2(a11, u23, np1);
                    }
                }
                unsigned long long* sa0 =
                    (unsigned long long*)&A[row0 * 520 + cbase + cc];
                sa0[0] = a00; sa0[1] = a01v;
                if (has2) {
                    unsigned long long* sa1 =
                        (unsigned long long*)&A[(row0 + 1) * 520 + cbase + cc];
                    sa1[0] = a10; sa1[1] = a11;
                }
            }
            __syncthreads();
        }
    }

    float* xs = P;
    const int lane = tid & 31, wid = tid >> 5;
    for (int r = 512; r >= 0; --r) {
        float part = 0.f;
        for (int c = r + 1 + tid; c <= 512; c += 512)
            part += A[r * 520 + c] * xs[c];
#pragma unroll
        for (int off = 16; off > 0; off >>= 1)
            part += __shfl_down_sync(0xffffffffu, part, off);
        if (lane == 0) red[wid] = part;
        __syncthreads();
        if (tid == 0) {
            float s = 0.f;
#pragma unroll
            for (int w2 = 0; w2 < 16; ++w2) s += red[w2];
            xs[r] = (A[r * 520 + 513] - s) / A[r * 520 + r];
        }
        __syncthreads();
    }
    for (int i2 = tid; i2 < 513; i2 += 512)
        out[b * 513 + i2] = xs[i2];
}

// ---------------------------------------------------------------------------
extern "C" void kernel_launch(void* const* d_in, const int* in_sizes, int n_in,
                              void* d_out, int out_size)
{
    const float* x   = (const float*)d_in[0];
    const float* Win = (const float*)d_in[1];
    const float* W1  = (const float*)d_in[2];
    const float* W2  = (const float*)d_in[3];
    float* out = (float*)d_out;

    cudaFuncSetAttribute(scan_diag,
                         cudaFuncAttributeMaxDynamicSharedMemorySize, SCAN_SMEM);

    for (int d = 0; d < 127; ++d) {
        int i_min = d > 63 ? d - 63 : 0;
        int i_max = d < 63 ? d : 63;
        dim3 grid(i_max - i_min + 1, 2, 2);
        scan_diag<<<grid, 256, SCAN_SMEM>>>(x, Win, W1, W2, d, i_min);
    }
    hth_kernel<<<dim3(45, 64), 256>>>();
    htu_kernel<<<dim3(64, 3), 256>>>(x);
    solve_kernel<<<64, 512>>>(out);
}

// round 13
// speedup vs baseline: 1.1987x; 1.0387x over previous
#include <cuda_runtime.h>

// Problem constants: B=64, H=64, W=64, n=256, NF=513, L=63*63=3969, alpha^2=25

__device__ float g_state[64 * 64 * 64 * 256];   // [cell=(i*64+j)][b][n]
__device__ float g_A[64 * 513 * 520];           // augmented [513 x 514] per batch, ld=520

// ---- packed f32x2 helpers (dual fp32 pipe) ---------------------------------
__device__ __forceinline__ unsigned long long pk2(float a, float b) {
    unsigned long long r;
    asm("mov.b64 %0,{%1,%2};" : "=l"(r) : "f"(a), "f"(b));
    return r;
}
__device__ __forceinline__ void fma2(unsigned long long& d,
                                     unsigned long long a, unsigned long long b) {
    asm("fma.rn.f32x2 %0,%1,%2,%0;" : "+l"(d) : "l"(a), "l"(b));
}
__device__ __forceinline__ void unpk2(unsigned long long v, float& a, float& b) {
    asm("mov.b64 {%0,%1},%2;" : "=f"(a), "=f"(b) : "l"(v));
}

// ---------------------------------------------------------------------------
// Phase 1: wavefront scan, one launch per anti-diagonal.  VERBATIM from the
// best passing build (R2, 9168us).
// ---------------------------------------------------------------------------
__global__ __launch_bounds__(256) void scan_diag(
    const float* __restrict__ x, const float* __restrict__ Win,
    const float* __restrict__ W1, const float* __restrict__ W2,
    int d, int i_min)
{
    __shared__ __align__(16) float in_s[2][32][34];   // [buf][k][b] (pad 34)
    __shared__ __align__(16) float w_s[2][32][128];   // [buf][k][n]

    const int i = i_min + (int)blockIdx.x;
    const int j = d - i;
    const int b0 = (int)blockIdx.y * 32;
    const int n0 = (int)blockIdx.z * 128;
    const int tid = (int)threadIdx.x;
    const int tx = tid & 31;    // n: 4 cols
    const int ty = tid >> 5;    // b: 4 rows (2 pairs)

    const bool hasL = (j > 0);
    const bool hasU = (i > 0);
    const int cellL = hasL ? ((i * 64 + (j - 1)) * 64) : 0;
    const int cellU = hasU ? (((i - 1) * 64 + j) * 64) : 0;

    const int bb = tid >> 3;   // 0..31 batch for input staging
    const int kq = tid & 7;    // 0..7  k-quad for input staging

    unsigned long long acc[2][4];
#pragma unroll
    for (int p = 0; p < 2; ++p)
#pragma unroll
        for (int c = 0; c < 4; ++c) acc[p][c] = 0ull;

    float4 inr;
    float4 wr[4];

    auto LOADC = [&](int kc) {
        const int k0 = kc * 32;
        const bool isLeft = (k0 < 256);
        const bool has = isLeft ? hasL : hasU;
        const int ks = isLeft ? k0 : (k0 - 256);
        inr = make_float4(0.f, 0.f, 0.f, 0.f);
        if (has) {
            const int cell = isLeft ? cellL : cellU;
            inr = *(const float4*)&g_state[(cell + b0 + bb) * 256 + ks + kq * 4];
        }
        const float* __restrict__ Wm = isLeft ? W1 : W2;
#pragma unroll
        for (int t = 0; t < 4; ++t) {
            int fi = tid + t * 256;
            int kl = fi >> 5;
            int cq = fi & 31;
            wr[t] = *(const float4*)&Wm[(ks + kl) * 256 + n0 + cq * 4];
        }
    };
    auto STOREC = [&](int buf) {
        in_s[buf][kq * 4 + 0][bb] = inr.x;
        in_s[buf][kq * 4 + 1][bb] = inr.y;
        in_s[buf][kq * 4 + 2][bb] = inr.z;
        in_s[buf][kq * 4 + 3][bb] = inr.w;
#pragma unroll
        for (int t = 0; t < 4; ++t) {
            int fi = tid + t * 256;
            int kl = fi >> 5;
            int cq = fi & 31;
            *(float4*)&w_s[buf][kl][cq * 4] = wr[t];
        }
    };

    LOADC(0);
    STOREC(0);

    for (int kc = 0; kc < 16; ++kc) {
        __syncthreads();
        if (kc < 15) LOADC(kc + 1);
        const int buf = kc & 1;
#pragma unroll 8
        for (int kl = 0; kl < 32; ++kl) {
            unsigned long long a01 = *(const unsigned long long*)&in_s[buf][kl][ty * 4];
            unsigned long long a23 = *(const unsigned long long*)&in_s[buf][kl][ty * 4 + 2];
            float4 w = *(const float4*)&w_s[buf][kl][tx * 4];
            unsigned long long wx = pk2(w.x, w.x);
            unsigned long long wy = pk2(w.y, w.y);
            unsigned long long wz = pk2(w.z, w.z);
            unsigned long long ww = pk2(w.w, w.w);
            fma2(acc[0][0], a01, wx); fma2(acc[0][1], a01, wy);
            fma2(acc[0][2], a01, wz); fma2(acc[0][3], a01, ww);
            fma2(acc[1][0], a23, wx); fma2(acc[1][1], a23, wy);
            fma2(acc[1][2], a23, wz); fma2(acc[1][3], a23, ww);
        }
        if (kc < 15) STOREC((kc + 1) & 1);
    }

    // epilogue: + x*Win, tanh, store
    const int cell = (i * 64 + j) * 64;
    float4 wv = *(const float4*)&Win[n0 + tx * 4];
#pragma unroll
    for (int p = 0; p < 2; ++p) {
        float lo0, hi0, lo1, hi1, lo2, hi2, lo3, hi3;
        unpk2(acc[p][0], lo0, hi0);
        unpk2(acc[p][1], lo1, hi1);
        unpk2(acc[p][2], lo2, hi2);
        unpk2(acc[p][3], lo3, hi3);
        const int bA = b0 + ty * 4 + 2 * p;
        const int bB = bA + 1;
        const float xA = x[(bA * 64 + i) * 64 + j];
        const float xB = x[(bB * 64 + i) * 64 + j];
        float4 oA, oB;
        oA.x = tanhf(lo0 + xA * wv.x); oA.y = tanhf(lo1 + xA * wv.y);
        oA.z = tanhf(lo2 + xA * wv.z); oA.w = tanhf(lo3 + xA * wv.w);
        oB.x = tanhf(hi0 + xB * wv.x); oB.y = tanhf(hi1 + xB * wv.y);
        oB.z = tanhf(hi2 + xB * wv.z); oB.w = tanhf(hi3 + xB * wv.w);
        *(float4*)&g_state[(cell + bA) * 256 + n0 + tx * 4] = oA;
        *(float4*)&g_state[(cell + bB) * 256 + n0 + tx * 4] = oB;
    }
}

// ---------------------------------------------------------------------------
// Phase 2a: HtH with 128x128 tiles (10 pairs over 4 column-groups), 512
// threads, 16 u64 accumulators/thread (no spills — the R11 failure mode).
// Per-output l-order: chunks of 32, kk ascending -> values bitwise == R11
// (which PASSED).  Rows/cols 0..511 only; row/col 512 handled by htu_kernel.
// ---------------------------------------------------------------------------
__global__ __launch_bounds__(512) void hth_kernel()
{
    __shared__ __align__(16) float Hd[32][128];
    __shared__ __align__(16) float He[32][128];

    int rem = (int)blockIdx.x;
    int ti = 0;
    while (rem >= 4 - ti) { rem -= 4 - ti; ++ti; }
    const int tj = ti + rem;
    const int b = (int)blockIdx.y;
    const int d0 = ti * 128, e0 = tj * 128;
    const bool dLeft = d0 < 256;
    const bool eLeft = e0 < 256;
    const int dColn = dLeft ? d0 : d0 - 256;
    const int eColn = eLeft ? e0 : e0 - 256;
    const bool diag = (ti == tj);

    const int tid = (int)threadIdx.x;
    const int tx = tid & 31;          // 4 e-cols at tx*4
    const int ty = tid >> 5;          // 8 d-rows at ty*8 (4 row-pairs)
    const int dd = tid & 127;         // staging column
    const int kb = tid >> 7;          // staging k-phase (0..3)

    unsigned long long acc[4][4];
#pragma unroll
    for (int rp = 0; rp < 4; ++rp)
#pragma unroll
        for (int c = 0; c < 4; ++c) acc[rp][c] = 0ull;

    for (int l0 = 0; l0 < 3969; l0 += 32) {
        __syncthreads();
#pragma unroll
        for (int t = 0; t < 8; ++t) {
            const int kk = kb + t * 4;
            const int l = l0 + kk;
            const bool valid = (l < 3969);
            float vd = 0.f, ve = 0.f;
            if (valid) {
                int r = l / 63;
                int c = l - r * 63;
                int cellD = dLeft ? ((r + 1) * 64 + c) : (r * 64 + c + 1);
                vd = g_state[(cellD * 64 + b) * 256 + dColn + dd];
                if (!diag) {
                    int cellE = eLeft ? ((r + 1) * 64 + c) : (r * 64 + c + 1);
                    ve = g_state[(cellE * 64 + b) * 256 + eColn + dd];
                }
            }
            Hd[kk][dd] = vd;
            if (!diag) He[kk][dd] = ve;
        }
        __syncthreads();

        const float (*Hep)[128] = diag ? Hd : He;
#pragma unroll 4
        for (int kk = 0; kk < 32; ++kk) {
            unsigned long long a0 = *(const unsigned long long*)&Hd[kk][ty * 8 + 0];
            unsigned long long a1 = *(const unsigned long long*)&Hd[kk][ty * 8 + 2];
            unsigned long long a2 = *(const unsigned long long*)&Hd[kk][ty * 8 + 4];
            unsigned long long a3 = *(const unsigned long long*)&Hd[kk][ty * 8 + 6];
            float4 w = *(const float4*)&Hep[kk][tx * 4];
            unsigned long long wx = pk2(w.x, w.x);
            unsigned long long wy = pk2(w.y, w.y);
            unsigned long long wz = pk2(w.z, w.z);
            unsigned long long ww = pk2(w.w, w.w);
            fma2(acc[0][0], a0, wx); fma2(acc[0][1], a0, wy);
            fma2(acc[0][2], a0, wz); fma2(acc[0][3], a0, ww);
            fma2(acc[1][0], a1, wx); fma2(acc[1][1], a1, wy);
            fma2(acc[1][2], a1, wz); fma2(acc[1][3], a1, ww);
            fma2(acc[2][0], a2, wx); fma2(acc[2][1], a2, wy);
            fma2(acc[2][2], a2, wz); fma2(acc[2][3], a2, ww);
            fma2(acc[3][0], a3, wx); fma2(acc[3][1], a3, wy);
            fma2(acc[3][2], a3, wz); fma2(acc[3][3], a3, ww);
        }
    }

    float* __restrict__ A = g_A + b * 513 * 520;
#pragma unroll
    for (int rp = 0; rp < 4; ++rp) {
        const int dr = d0 + ty * 8 + rp * 2;
#pragma unroll
        for (int c = 0; c < 4; ++c) {
            const int e = e0 + tx * 4 + c;
            float va, vb;
            unpk2(acc[rp][c], va, vb);
            if (dr == e) va += 25.0f;
            if (dr + 1 == e) vb += 25.0f;
            A[dr * 520 + e] = va;
            A[(dr + 1) * 520 + e] = vb;
            if (!diag) {
                A[e * 520 + dr] = va;
                A[e * 520 + dr + 1] = vb;
            }
        }
    }
}

// ---------------------------------------------------------------------------
// Phase 2b: HtU (RHS col 513) + ones row/col 512, fused.  VERBATIM from R11
// (which PASSED with rel_err 5.819513e-4).  Sequential (r,c) order per
// accumulator — do NOT reassociate (R4 lesson).
// ---------------------------------------------------------------------------
__global__ __launch_bounds__(256) void htu_kernel(const float* __restrict__ x)
{
    const int b = (int)blockIdx.x;
    const int dcol = (int)blockIdx.y * 256 + (int)threadIdx.x;
    if (dcol > 512) return;
    const float* __restrict__ xb = x + b * 4096;
    float* __restrict__ A = g_A + b * 513 * 520;

    if (dcol < 512) {
        const bool left = (dcol < 256);
        const int d2 = left ? dcol : dcol - 256;
        float acct = 0.f;
        float acc1 = 0.f;
        for (int r = 0; r < 63; ++r)
            for (int c = 0; c < 63; ++c) {
                int cellb = left ? ((r + 1) * 64 + c) : (r * 64 + c + 1);
                float h = g_state[(cellb * 64 + b) * 256 + d2];
                acct += xb[(r + 1) * 64 + c + 1] * h;
                acc1 += h;
            }
        A[dcol * 520 + 513] = acct;
        A[512 * 520 + dcol] = acc1;
        A[dcol * 520 + 512] = acc1;
    } else {
        float acct = 0.f;
        for (int r = 0; r < 63; ++r)
            for (int c = 0; c < 63; ++c)
                acct += xb[(r + 1) * 64 + c + 1];
        A[512 * 520 + 513] = acct;
        A[512 * 520 + 512] = 3969.0f + 25.0f;
    }
}

// ---------------------------------------------------------------------------
// Phase 3: per-batch blocked LU (no pivoting; SPD) + back substitution.
// VERBATIM from the 9168us build.
// ---------------------------------------------------------------------------
__global__ __launch_bounds__(512) void solve_kernel(float* __restrict__ out)
{
    __shared__ float P[513 * 17];
    __shared__ __align__(16) float Us[16 * 132];
    __shared__ float red[16];

    const int b = (int)blockIdx.x;
    const int tid = (int)threadIdx.x;
    float* __restrict__ A = g_A + b * 513 * 520;

    for (int k0 = 0; k0 < 513; k0 += 16) {
        const int nb = (513 - k0) < 16 ? (513 - k0) : 16;
        const int nrows = 513 - k0;

        for (int idx = tid; idx < nrows * nb; idx += 512) {
            int rr = idx / nb, cc = idx - rr * nb;
            P[rr * 17 + cc] = A[(k0 + rr) * 520 + (k0 + cc)];
        }
        __syncthreads();

        for (int kk = 0; kk < nb; ++kk) {
            float inv = 1.0f / P[kk * 17 + kk];
            for (int rr = kk + 1 + tid; rr < nrows; rr += 512) {
                float lv = P[rr * 17 + kk] * inv;
                P[rr * 17 + kk] = lv;
                for (int cc = kk + 1; cc < nb; ++cc)
                    P[rr * 17 + cc] -= lv * P[kk * 17 + cc];
            }
            __syncthreads();
        }

        for (int idx = tid; idx < nrows * nb; idx += 512) {
            int rr = idx / nb, cc = idx - rr * nb;
            A[(k0 + rr) * 520 + (k0 + cc)] = P[rr * 17 + cc];
        }
        __syncthreads();

        const int cstart = k0 + nb;
        const int width = 514 - cstart;
        for (int ch = 0; ch < width; ch += 128) {
            int wlen = width - ch; if (wlen > 128) wlen = 128;
            const int wlenp = (wlen + 3) & ~3;
            const int cbase = cstart + ch;

            for (int idx = tid; idx < nb * wlenp; idx += 512) {
                int rr = idx / wlenp, cc = idx - rr * wlenp;
                Us[rr * 132 + cc] = A[(k0 + rr) * 520 + cbase + cc];
            }
            __syncthreads();

            for (int cc = tid; cc < wlenp; cc += 512) {
                float col[16];
                for (int m = 0; m < nb; ++m) col[m] = Us[m * 132 + cc];
                for (int kk = 1; kk < nb; ++kk) {
                    float v = col[kk];
                    for (int m = 0; m < kk; ++m) v -= P[kk * 17 + m] * col[m];
                    col[kk] = v;
                }
                for (int m = 0; m < nb; ++m) {
                    Us[m * 132 + cc] = col[m];
                    A[(k0 + m) * 520 + cbase + cc] = col[m];
                }
            }
            __syncthreads();

            const int trows = nrows - nb;
            const int npr = (trows + 1) >> 1;
            const int ncq = wlenp >> 2;
            for (int idx = tid; idx < npr * ncq; idx += 512) {
                int pr = idx / ncq, cq = idx - pr * ncq;
                int row0 = cstart + pr * 2;
                int cc = cq * 4;
                bool has2 = (pr * 2 + 1) < trows;
                const unsigned long long* pa0 =
                    (const unsigned long long*)&A[row0 * 520 + cbase + cc];
                const unsigned long long* pa1 =
                    (const unsigned long long*)&A[(row0 + 1) * 520 + cbase + cc];
                unsigned long long a00 = pa0[0], a01v = pa0[1];
                unsigned long long a10 = has2 ? pa1[0] : a00;
                unsigned long long a11 = has2 ? pa1[1] : a01v;
                const float* P0 = &P[(row0 - k0) * 17];
                const float* P1 = has2 ? (P0 + 17) : P0;
#pragma unroll
                for (int m = 0; m < 16; ++m) {
                    if (m < nb) {
                        const unsigned long long* pu =
                            (const unsigned long long*)&Us[m * 132 + cc];
                        unsigned long long u01 = pu[0], u23 = pu[1];
                        float p0 = P0[m], p1 = P1[m];
                        unsigned long long np0 = pk2(-p0, -p0);
                        unsigned long long np1 = pk2(-p1, -p1);
                        fma2(a00, u01, np0); fma2(a01v, u23, np0);
                        fma2(a10, u01, np1); fma2(a11, u23, np1);
                    }
                }
                unsigned long long* sa0 =
                    (unsigned long long*)&A[row0 * 520 + cbase + cc];
                sa0[0] = a00; sa0[1] = a01v;
                if (has2) {
                    unsigned long long* sa1 =
                        (unsigned long long*)&A[(row0 + 1) * 520 + cbase + cc];
                    sa1[0] = a10; sa1[1] = a11;
                }
            }
            __syncthreads();
        }
    }

    float* xs = P;
    const int lane = tid & 31, wid = tid >> 5;
    for (int r = 512; r >= 0; --r) {
        float part = 0.f;
        for (int c = r + 1 + tid; c <= 512; c += 512)
            part += A[r * 520 + c] * xs[c];
#pragma unroll
        for (int off = 16; off > 0; off >>= 1)
            part += __shfl_down_sync(0xffffffffu, part, off);
        if (lane == 0) red[wid] = part;
        __syncthreads();
        if (tid == 0) {
            float s = 0.f;
#pragma unroll
            for (int w2 = 0; w2 < 16; ++w2) s += red[w2];
            xs[r] = (A[r * 520 + 513] - s) / A[r * 520 + r];
        }
        __syncthreads();
    }
    for (int i2 = tid; i2 < 513; i2 += 512)
        out[b * 513 + i2] = xs[i2];
}

// ---------------------------------------------------------------------------
extern "C" void kernel_launch(void* const* d_in, const int* in_sizes, int n_in,
                              void* d_out, int out_size)
{
    const float* x   = (const float*)d_in[0];
    const float* Win = (const float*)d_in[1];
    const float* W1  = (const float*)d_in[2];
    const float* W2  = (const float*)d_in[3];
    float* out = (float*)d_out;

    for (int d = 0; d < 127; ++d) {
        int i_min = d > 63 ? d - 63 : 0;
        int i_max = d < 63 ? d : 63;
        dim3 grid(i_max - i_min + 1, 2, 2);
        scan_diag<<<grid, 256>>>(x, Win, W1, W2, d, i_min);
    }
    hth_kernel<<<dim3(10, 64), 512>>>();
    htu_kernel<<<dim3(64, 3), 256>>>(x);
    solve_kernel<<<64, 512>>>(out);
}

// round 14
// speedup vs baseline: 1.4089x; 1.1753x over previous
#include <cuda_runtime.h>

// Problem constants: B=64, H=64, W=64, n=256, NF=513, L=63*63=3969, alpha^2=25

__device__ float g_state[64 * 64 * 64 * 256];   // [cell=(i*64+j)][b][n]
__device__ float g_A[64 * 513 * 520];           // augmented [513 x 514] per batch, ld=520

// ---- packed f32x2 helpers (dual fp32 pipe) ---------------------------------
__device__ __forceinline__ unsigned long long pk2(float a, float b) {
    unsigned long long r;
    asm("mov.b64 %0,{%1,%2};" : "=l"(r) : "f"(a), "f"(b));
    return r;
}
__device__ __forceinline__ void fma2(unsigned long long& d,
                                     unsigned long long a, unsigned long long b) {
    asm("fma.rn.f32x2 %0,%1,%2,%0;" : "+l"(d) : "l"(a), "l"(b));
}
__device__ __forceinline__ void unpk2(unsigned long long v, float& a, float& b) {
    asm("mov.b64 {%0,%1},%2;" : "=f"(a), "=f"(b) : "l"(v));
}

// ---- cp.async helpers -------------------------------------------------------
__device__ __forceinline__ void cp4(unsigned int dst, const void* src, int srcsize) {
    asm volatile("cp.async.ca.shared.global [%0], [%1], 4, %2;"
                 :: "r"(dst), "l"(src), "r"(srcsize) : "memory");
}
__device__ __forceinline__ void cp16(unsigned int dst, const void* src) {
    asm volatile("cp.async.cg.shared.global [%0], [%1], 16;"
                 :: "r"(dst), "l"(src) : "memory");
}
#define CP_COMMIT() asm volatile("cp.async.commit_group;" ::: "memory")
#define CP_WAIT1()  asm volatile("cp.async.wait_group 1;" ::: "memory")
#define CP_WAIT0()  asm volatile("cp.async.wait_group 0;" ::: "memory")

__device__ __forceinline__ unsigned int smem_u32(const void* p) {
    return (unsigned int)__cvta_generic_to_shared(p);
}

// ---------------------------------------------------------------------------
// Phase 1: wavefront scan, one launch per anti-diagonal.  R2 tiling and
// compute loop EXACTLY; W staging converted to cp.async (3 buffers, depth-2
// prefetch, one barrier per chunk).  Input keeps the register path (needs a
// transpose).  Values bitwise identical to the 9168us build.
// ---------------------------------------------------------------------------
#define SCAN_SMEM ((3 * 32 * 128 + 2 * 32 * 34) * 4)   // 49152 + 8704 = 57856

__global__ __launch_bounds__(256) void scan_diag(
    const float* __restrict__ x, const float* __restrict__ Win,
    const float* __restrict__ W1, const float* __restrict__ W2,
    int d, int i_min)
{
    extern __shared__ float sm[];
    float (*w_s)[32][128] = (float(*)[32][128])sm;           // [3][32][128]
    float (*in_s)[32][34] = (float(*)[32][34])(sm + 3 * 32 * 128); // [2][32][34]

    const int i = i_min + (int)blockIdx.x;
    const int j = d - i;
    const int b0 = (int)blockIdx.y * 32;
    const int n0 = (int)blockIdx.z * 128;
    const int tid = (int)threadIdx.x;
    const int tx = tid & 31;    // n: 4 cols
    const int ty = tid >> 5;    // b: 4 rows (2 pairs)

    const bool hasL = (j > 0);
    const bool hasU = (i > 0);
    const int cellL = hasL ? ((i * 64 + (j - 1)) * 64) : 0;
    const int cellU = hasU ? (((i - 1) * 64 + j) * 64) : 0;

    const int bb = tid >> 3;   // 0..31 batch for input staging
    const int kq = tid & 7;    // 0..7  k-quad for input staging

    const unsigned int w_base = smem_u32(&w_s[0][0][0]);

    unsigned long long acc[2][4];
#pragma unroll
    for (int p = 0; p < 2; ++p)
#pragma unroll
        for (int c = 0; c < 4; ++c) acc[p][c] = 0ull;

    float4 inr;

    auto CPW = [&](int kc, int buf) {
        const int k0 = kc * 32;
        const float* __restrict__ Wm = (k0 < 256) ? W1 : W2;
        const int ks = (k0 < 256) ? k0 : (k0 - 256);
        const unsigned int base = w_base + (unsigned int)buf * (32 * 128 * 4);
#pragma unroll
        for (int t = 0; t < 4; ++t) {
            int fi = tid + t * 256;
            int kl = fi >> 5;
            int cq = fi & 31;
            cp16(base + (unsigned int)(kl * 128 + cq * 4) * 4,
                 &Wm[(ks + kl) * 256 + n0 + cq * 4]);
        }
        CP_COMMIT();
    };
    auto LOADI = [&](int kc) {
        const int k0 = kc * 32;
        const bool isLeft = (k0 < 256);
        const bool has = isLeft ? hasL : hasU;
        const int ks = isLeft ? k0 : (k0 - 256);
        inr = make_float4(0.f, 0.f, 0.f, 0.f);
        if (has) {
            const int cell = isLeft ? cellL : cellU;
            inr = *(const float4*)&g_state[(cell + b0 + bb) * 256 + ks + kq * 4];
        }
    };
    auto STOREI = [&](int buf) {
        in_s[buf][kq * 4 + 0][bb] = inr.x;
        in_s[buf][kq * 4 + 1][bb] = inr.y;
        in_s[buf][kq * 4 + 2][bb] = inr.z;
        in_s[buf][kq * 4 + 3][bb] = inr.w;
    };

    // prologue: W chunks 0 and 1 in flight; input chunk 0 staged
    CPW(0, 0);
    CPW(1, 1);
    LOADI(0);
    STOREI(0);

    int bw = 0;   // W buffer for current chunk (kc % 3)
    for (int kc = 0; kc < 16; ++kc) {
        if (kc < 15) CP_WAIT1(); else CP_WAIT0();
        __syncthreads();    // W(kc) + in_s(kc) visible; WAR guard for stages below

        if (kc < 14) {
            int bw2 = bw + 2; if (bw2 >= 3) bw2 -= 3;
            CPW(kc + 2, bw2);
        }
        if (kc < 15) LOADI(kc + 1);

        const int bufi = kc & 1;
#pragma unroll 8
        for (int kl = 0; kl < 32; ++kl) {
            unsigned long long a01 = *(const unsigned long long*)&in_s[bufi][kl][ty * 4];
            unsigned long long a23 = *(const unsigned long long*)&in_s[bufi][kl][ty * 4 + 2];
            float4 w = *(const float4*)&w_s[bw][kl][tx * 4];
            unsigned long long wx = pk2(w.x, w.x);
            unsigned long long wy = pk2(w.y, w.y);
            unsigned long long wz = pk2(w.z, w.z);
            unsigned long long ww = pk2(w.w, w.w);
            fma2(acc[0][0], a01, wx); fma2(acc[0][1], a01, wy);
            fma2(acc[0][2], a01, wz); fma2(acc[0][3], a01, ww);
            fma2(acc[1][0], a23, wx); fma2(acc[1][1], a23, wy);
            fma2(acc[1][2], a23, wz); fma2(acc[1][3], a23, ww);
        }
        if (kc < 15) STOREI((kc + 1) & 1);
        bw = (bw == 2) ? 0 : bw + 1;
    }

    // epilogue: + x*Win, tanh, store
    const int cell = (i * 64 + j) * 64;
    float4 wv = *(const float4*)&Win[n0 + tx * 4];
#pragma unroll
    for (int p = 0; p < 2; ++p) {
        float lo0, hi0, lo1, hi1, lo2, hi2, lo3, hi3;
        unpk2(acc[p][0], lo0, hi0);
        unpk2(acc[p][1], lo1, hi1);
        unpk2(acc[p][2], lo2, hi2);
        unpk2(acc[p][3], lo3, hi3);
        const int bA = b0 + ty * 4 + 2 * p;
        const int bB = bA + 1;
        const float xA = x[(bA * 64 + i) * 64 + j];
        const float xB = x[(bB * 64 + i) * 64 + j];
        float4 oA, oB;
        oA.x = tanhf(lo0 + xA * wv.x); oA.y = tanhf(lo1 + xA * wv.y);
        oA.z = tanhf(lo2 + xA * wv.z); oA.w = tanhf(lo3 + xA * wv.w);
        oB.x = tanhf(hi0 + xB * wv.x); oB.y = tanhf(hi1 + xB * wv.y);
        oB.z = tanhf(hi2 + xB * wv.z); oB.w = tanhf(hi3 + xB * wv.w);
        *(float4*)&g_state[(cell + bA) * 256 + n0 + tx * 4] = oA;
        *(float4*)&g_state[(cell + bB) * 256 + n0 + tx * 4] = oB;
    }
}

// ---------------------------------------------------------------------------
// Phase 2a: HtH = 64x64 tiles, 45 pairs (R2 shape), but staging via cp.async
// into a 3-buffer pipeline (depth-2 prefetch, one barrier per chunk, zfill
// for l >= 3969, plain stores for the ones-group col 512).  Compute loop and
// output identical to R2 -> values bitwise identical.
// ---------------------------------------------------------------------------
#define HTH_SMEM (3 * 2 * 32 * 64 * 4)   // 49152

__global__ __launch_bounds__(256) void hth_kernel()
{
    extern __shared__ float hsm[];
    float (*Hd)[32][64] = (float(*)[32][64])hsm;                 // [3][32][64]
    float (*He)[32][64] = (float(*)[32][64])(hsm + 3 * 32 * 64); // [3][32][64]

    int rem = (int)blockIdx.x;
    int ti = 0;
    while (rem >= 9 - ti) { rem -= 9 - ti; ++ti; }
    const int tj = ti + rem;
    const int b = (int)blockIdx.y;
    const int d0 = ti * 64, e0 = tj * 64;
    const bool dLeft = d0 < 256, dOnes = d0 >= 512;
    const bool eLeft = e0 < 256, eOnes = e0 >= 512;
    const int dColn = dLeft ? d0 : d0 - 256;
    const int eColn = eLeft ? e0 : e0 - 256;

    const int tid = (int)threadIdx.x;
    const int tx = tid & 15, ty = tid >> 4;
    const int dd = tid & 63, kb = tid >> 6;

    const unsigned int hd_base = smem_u32(&Hd[0][0][0]);
    const unsigned int he_base = smem_u32(&He[0][0][0]);

    auto STAGE = [&](int l0, int buf) {
        const unsigned int db = hd_base + (unsigned int)buf * (32 * 64 * 4);
        const unsigned int eb = he_base + (unsigned int)buf * (32 * 64 * 4);
#pragma unroll
        for (int t = 0; t < 8; ++t) {
            const int kk = kb + t * 4;
            const int l = l0 + kk;
            const bool valid = (l < 3969);
            const int lc = valid ? l : 0;
            const int r = lc / 63;
            const int c = lc - r * 63;
            const int sz = valid ? 4 : 0;
            const unsigned int off = (unsigned int)(kk * 64 + dd) * 4;
            if (dOnes) {
                Hd[buf][kk][dd] = (valid && dd == 0) ? 1.f : 0.f;
            } else {
                int cellD = dLeft ? ((r + 1) * 64 + c) : (r * 64 + c + 1);
                cp4(db + off, &g_state[(cellD * 64 + b) * 256 + dColn + dd], sz);
            }
            if (eOnes) {
                He[buf][kk][dd] = (valid && dd == 0) ? 1.f : 0.f;
            } else {
                int cellE = eLeft ? ((r + 1) * 64 + c) : (r * 64 + c + 1);
                cp4(eb + off, &g_state[(cellE * 64 + b) * 256 + eColn + dd], sz);
            }
        }
        CP_COMMIT();
    };

    unsigned long long acc[2][4];
#pragma unroll
    for (int p = 0; p < 2; ++p)
#pragma unroll
        for (int c = 0; c < 4; ++c) acc[p][c] = 0ull;

    STAGE(0, 0);
    STAGE(32, 1);

    int bw = 0;
    for (int ch = 0; ch < 125; ++ch) {
        if (ch < 124) CP_WAIT1(); else CP_WAIT0();
        __syncthreads();

        if (ch < 123) {
            int bw2 = bw + 2; if (bw2 >= 3) bw2 -= 3;
            STAGE((ch + 2) * 32, bw2);
        }

#pragma unroll 8
        for (int kk = 0; kk < 32; ++kk) {
            unsigned long long a01 = *(const unsigned long long*)&Hd[bw][kk][ty * 4];
            unsigned long long a23 = *(const unsigned long long*)&Hd[bw][kk][ty * 4 + 2];
            float4 w = *(const float4*)&He[bw][kk][tx * 4];
            unsigned long long wx = pk2(w.x, w.x);
            unsigned long long wy = pk2(w.y, w.y);
            unsigned long long wz = pk2(w.z, w.z);
            unsigned long long ww = pk2(w.w, w.w);
            fma2(acc[0][0], a01, wx); fma2(acc[0][1], a01, wy);
            fma2(acc[0][2], a01, wz); fma2(acc[0][3], a01, ww);
            fma2(acc[1][0], a23, wx); fma2(acc[1][1], a23, wy);
            fma2(acc[1][2], a23, wz); fma2(acc[1][3], a23, ww);
        }
        bw = (bw == 2) ? 0 : bw + 1;
    }

    float v[4][4];
#pragma unroll
    for (int p = 0; p < 2; ++p)
#pragma unroll
        for (int c = 0; c < 4; ++c)
            unpk2(acc[p][c], v[2 * p][c], v[2 * p + 1][c]);

    float* __restrict__ A = g_A + b * 513 * 520;
#pragma unroll
    for (int r = 0; r < 4; ++r) {
        int dr = d0 + ty * 4 + r;
        if (dr >= 513) continue;
#pragma unroll
        for (int c = 0; c < 4; ++c) {
            int e = e0 + tx * 4 + c;
            if (e >= 513) continue;
            float val = v[r][c];
            if (dr == e) val += 25.0f;
            A[dr * 520 + e] = val;
            if (ti != tj) A[e * 520 + dr] = val;
        }
    }
}

// ---------------------------------------------------------------------------
// Phase 2b: HtU -> column 513 of A.  VERBATIM from the 9168us build.
// Sequential (r,c) numerics — do NOT reassociate (R4 lesson).
// ---------------------------------------------------------------------------
__global__ __launch_bounds__(256) void htu_kernel(const float* __restrict__ x)
{
    const int b = (int)blockIdx.x;
    const int dcol = (int)blockIdx.y * 256 + (int)threadIdx.x;
    if (dcol >= 513) return;
    const float* __restrict__ xb = x + b * 4096;
    float acc = 0.f;
    if (dcol < 256) {
        for (int r = 0; r < 63; ++r)
            for (int c = 0; c < 63; ++c)
                acc += xb[(r + 1) * 64 + c + 1] *
                       g_state[(((r + 1) * 64 + c) * 64 + b) * 256 + dcol];
    } else if (dcol < 512) {
        const int d2 = dcol - 256;
        for (int r = 0; r < 63; ++r)
            for (int c = 0; c < 63; ++c)
                acc += xb[(r + 1) * 64 + c + 1] *
                       g_state[((r * 64 + (c + 1)) * 64 + b) * 256 + d2];
    } else {
        for (int r = 0; r < 63; ++r)
            for (int c = 0; c < 63; ++c)
                acc += xb[(r + 1) * 64 + c + 1];
    }
    g_A[(b * 513 + dcol) * 520 + 513] = acc;
}

// ---------------------------------------------------------------------------
// Phase 3: per-batch blocked LU (no pivoting; SPD) + back substitution.
// VERBATIM from the 9168us build.
// ---------------------------------------------------------------------------
__global__ __launch_bounds__(512) void solve_kernel(float* __restrict__ out)
{
    __shared__ float P[513 * 17];
    __shared__ __align__(16) float Us[16 * 132];
    __shared__ float red[16];

    const int b = (int)blockIdx.x;
    const int tid = (int)threadIdx.x;
    float* __restrict__ A = g_A + b * 513 * 520;

    for (int k0 = 0; k0 < 513; k0 += 16) {
        const int nb = (513 - k0) < 16 ? (513 - k0) : 16;
        const int nrows = 513 - k0;

        for (int idx = tid; idx < nrows * nb; idx += 512) {
            int rr = idx / nb, cc = idx - rr * nb;
            P[rr * 17 + cc] = A[(k0 + rr) * 520 + (k0 + cc)];
        }
        __syncthreads();

        for (int kk = 0; kk < nb; ++kk) {
            float inv = 1.0f / P[kk * 17 + kk];
            for (int rr = kk + 1 + tid; rr < nrows; rr += 512) {
                float lv = P[rr * 17 + kk] * inv;
                P[rr * 17 + kk] = lv;
                for (int cc = kk + 1; cc < nb; ++cc)
                    P[rr * 17 + cc] -= lv * P[kk * 17 + cc];
            }
            __syncthreads();
        }

        for (int idx = tid; idx < nrows * nb; idx += 512) {
            int rr = idx / nb, cc = idx - rr * nb;
            A[(k0 + rr) * 520 + (k0 + cc)] = P[rr * 17 + cc];
        }
        __syncthreads();

        const int cstart = k0 + nb;
        const int width = 514 - cstart;
        for (int ch = 0; ch < width; ch += 128) {
            int wlen = width - ch; if (wlen > 128) wlen = 128;
            const int wlenp = (wlen + 3) & ~3;
            const int cbase = cstart + ch;

            for (int idx = tid; idx < nb * wlenp; idx += 512) {
                int rr = idx / wlenp, cc = idx - rr * wlenp;
                Us[rr * 132 + cc] = A[(k0 + rr) * 520 + cbase + cc];
            }
            __syncthreads();

            for (int cc = tid; cc < wlenp; cc += 512) {
                float col[16];
                for (int m = 0; m < nb; ++m) col[m] = Us[m * 132 + cc];
                for (int kk = 1; kk < nb; ++kk) {
                    float v = col[kk];
                    for (int m = 0; m < kk; ++m) v -= P[kk * 17 + m] * col[m];
                    col[kk] = v;
                }
                for (int m = 0; m < nb; ++m) {
                    Us[m * 132 + cc] = col[m];
                    A[(k0 + m) * 520 + cbase + cc] = col[m];
                }
            }
            __syncthreads();

            const int trows = nrows - nb;
            const int npr = (trows + 1) >> 1;
            const int ncq = wlenp >> 2;
            for (int idx = tid; idx < npr * ncq; idx += 512) {
                int pr = idx / ncq, cq = idx - pr * ncq;
                int row0 = cstart + pr * 2;
                int cc = cq * 4;
                bool has2 = (pr * 2 + 1) < trows;
                const unsigned long long* pa0 =
                    (const unsigned long long*)&A[row0 * 520 + cbase + cc];
                const unsigned long long* pa1 =
                    (const unsigned long long*)&A[(row0 + 1) * 520 + cbase + cc];
                unsigned long long a00 = pa0[0], a01v = pa0[1];
                unsigned long long a10 = has2 ? pa1[0] : a00;
                unsigned long long a11 = has2 ? pa1[1] : a01v;
                const float* P0 = &P[(row0 - k0) * 17];
                const float* P1 = has2 ? (P0 + 17) : P0;
#pragma unroll
                for (int m = 0; m < 16; ++m) {
                    if (m < nb) {
                        const unsigned long long* pu =
                            (const unsigned long long*)&Us[m * 132 + cc];
                        unsigned long long u01 = pu[0], u23 = pu[1];
                        float p0 = P0[m], p1 = P1[m];
                        unsigned long long np0 = pk2(-p0, -p0);
                        unsigned long long np1 = pk2(-p1, -p1);
                        fma2(a00, u01, np0); fma2(a01v, u23, np0);
                        fma2(a10, u01, np1); fma2(a11, u23, np1);
                    }
                }
                unsigned long long* sa0 =
                    (unsigned long long*)&A[row0 * 520 + cbase + cc];
                sa0[0] = a00; sa0[1] = a01v;
                if (has2) {
                    unsigned long long* sa1 =
                        (unsigned long long*)&A[(row0 + 1) * 520 + cbase + cc];
                    sa1[0] = a10; sa1[1] = a11;
                }
            }
            __syncthreads();
        }
    }

    float* xs = P;
    const int lane = tid & 31, wid = tid >> 5;
    for (int r = 512; r >= 0; --r) {
        float part = 0.f;
        for (int c = r + 1 + tid; c <= 512; c += 512)
            part += A[r * 520 + c] * xs[c];
#pragma unroll
        for (int off = 16; off > 0; off >>= 1)
            part += __shfl_down_sync(0xffffffffu, part, off);
        if (lane == 0) red[wid] = part;
        __syncthreads();
        if (tid == 0) {
            float s = 0.f;
#pragma unroll
            for (int w2 = 0; w2 < 16; ++w2) s += red[w2];
            xs[r] = (A[r * 520 + 513] - s) / A[r * 520 + r];
        }
        __syncthreads();
    }
    for (int i2 = tid; i2 < 513; i2 += 512)
        out[b * 513 + i2] = xs[i2];
}

// ---------------------------------------------------------------------------
extern "C" void kernel_launch(void* const* d_in, const int* in_sizes, int n_in,
                              void* d_out, int out_size)
{
    const float* x   = (const float*)d_in[0];
    const float* Win = (const float*)d_in[1];
    const float* W1  = (const float*)d_in[2];
    const float* W2  = (const float*)d_in[3];
    float* out = (float*)d_out;

    static bool attr_set = false;
    if (!attr_set) {
        cudaFuncSetAttribute(scan_diag,
                             cudaFuncAttributeMaxDynamicSharedMemorySize, SCAN_SMEM);
        cudaFuncSetAttribute(hth_kernel,
                             cudaFuncAttributeMaxDynamicSharedMemorySize, HTH_SMEM);
        attr_set = true;
    }

    for (int d = 0; d < 127; ++d) {
        int i_min = d > 63 ? d - 63 : 0;
        int i_max = d < 63 ? d : 63;
        dim3 grid(i_max - i_min + 1, 2, 2);
        scan_diag<<<grid, 256, SCAN_SMEM>>>(x, Win, W1, W2, d, i_min);
    }
    hth_kernel<<<dim3(45, 64), 256, HTH_SMEM>>>();
    htu_kernel<<<dim3(64, 3), 256>>>(x);
    solve_kernel<<<64, 512>>>(out);
}

// round 15
// speedup vs baseline: 1.4449x; 1.0256x over previous
#include <cuda_runtime.h>

// Problem constants: B=64, H=64, W=64, n=256, NF=513, L=63*63=3969, alpha^2=25

__device__ float g_state[64 * 64 * 64 * 256];   // [cell=(i*64+j)][b][n]
__device__ float g_A[64 * 513 * 520];           // augmented [513 x 514] per batch, ld=520

// ---- packed f32x2 helpers (dual fp32 pipe) ---------------------------------
__device__ __forceinline__ unsigned long long pk2(float a, float b) {
    unsigned long long r;
    asm("mov.b64 %0,{%1,%2};" : "=l"(r) : "f"(a), "f"(b));
    return r;
}
__device__ __forceinline__ void fma2(unsigned long long& d,
                                     unsigned long long a, unsigned long long b) {
    asm("fma.rn.f32x2 %0,%1,%2,%0;" : "+l"(d) : "l"(a), "l"(b));
}
__device__ __forceinline__ void unpk2(unsigned long long v, float& a, float& b) {
    asm("mov.b64 {%0,%1},%2;" : "=f"(a), "=f"(b) : "l"(v));
}

// ---- cp.async helpers -------------------------------------------------------
__device__ __forceinline__ void cp16(unsigned int dst, const void* src) {
    asm volatile("cp.async.cg.shared.global [%0], [%1], 16;"
                 :: "r"(dst), "l"(src) : "memory");
}
__device__ __forceinline__ void cp16z(unsigned int dst, const void* src, int srcsize) {
    asm volatile("cp.async.cg.shared.global [%0], [%1], 16, %2;"
                 :: "r"(dst), "l"(src), "r"(srcsize) : "memory");
}
#define CP_COMMIT() asm volatile("cp.async.commit_group;" ::: "memory")
#define CP_WAIT1()  asm volatile("cp.async.wait_group 1;" ::: "memory")
#define CP_WAIT0()  asm volatile("cp.async.wait_group 0;" ::: "memory")

__device__ __forceinline__ unsigned int smem_u32(const void* p) {
    return (unsigned int)__cvta_generic_to_shared(p);
}

// ---------------------------------------------------------------------------
// Phase 1: wavefront scan, one launch per anti-diagonal.
// grid = (cells, 2 batch-halves, 4 n-quarters): 8 blocks/cell (2x the
// parallelism of the R2 shape at IDENTICAL per-cell W traffic — n-slices are
// disjoint).  256 threads, tile 32 batches x 64 features, k-chunk 32.
// W staged by cp16 (3 buffers, depth-2); input via the R2 register path.
// Per-output k order ascending 0..511, one accumulator -> bitwise == R2/R14.
// ---------------------------------------------------------------------------
#define SCAN_SMEM ((3 * 32 * 64 + 2 * 32 * 34) * 4)   // 24576 + 8704 = 33280

__global__ __launch_bounds__(256) void scan_diag(
    const float* __restrict__ x, const float* __restrict__ Win,
    const float* __restrict__ W1, const float* __restrict__ W2,
    int d, int i_min)
{
    extern __shared__ float sm[];
    float (*w_s)[32][64]  = (float(*)[32][64])sm;                 // [3][32][64]
    float (*in_s)[32][34] = (float(*)[32][34])(sm + 3 * 32 * 64); // [2][32][34]

    const int i = i_min + (int)blockIdx.x;
    const int j = d - i;
    const int b0 = (int)blockIdx.y * 32;
    const int n0 = (int)blockIdx.z * 64;
    const int tid = (int)threadIdx.x;
    const int tx = tid & 15;    // n: 4 cols at n0 + tx*4
    const int ty = tid >> 4;    // batch pair: b0 + ty*2, +1

    const bool hasL = (j > 0);
    const bool hasU = (i > 0);
    const int cellL = hasL ? ((i * 64 + (j - 1)) * 64) : 0;
    const int cellU = hasU ? (((i - 1) * 64 + j) * 64) : 0;

    const int bb = tid >> 3;   // 0..31 batch for input staging
    const int kq = tid & 7;    // 0..7  k-quad for input staging

    const unsigned int w_base = smem_u32(&w_s[0][0][0]);

    unsigned long long acc[4];
    acc[0] = acc[1] = acc[2] = acc[3] = 0ull;

    float4 inr;

    auto CPW = [&](int kc, int buf) {
        const int k0 = kc * 32;
        const float* __restrict__ Wm = (k0 < 256) ? W1 : W2;
        const int ks = (k0 < 256) ? k0 : (k0 - 256);
        const unsigned int base = w_base + (unsigned int)buf * (32 * 64 * 4);
#pragma unroll
        for (int t = 0; t < 2; ++t) {
            int idx = tid + t * 256;       // 0..511
            int kl = idx >> 4;             // 0..31
            int q  = idx & 15;             // 0..15
            cp16(base + (unsigned int)(kl * 64 + q * 4) * 4,
                 &Wm[(ks + kl) * 256 + n0 + q * 4]);
        }
        CP_COMMIT();
    };
    auto LOADI = [&](int kc) {
        const int k0 = kc * 32;
        const bool isLeft = (k0 < 256);
        const bool has = isLeft ? hasL : hasU;
        const int ks = isLeft ? k0 : (k0 - 256);
        inr = make_float4(0.f, 0.f, 0.f, 0.f);
        if (has) {
            const int cell = isLeft ? cellL : cellU;
            inr = *(const float4*)&g_state[(cell + b0 + bb) * 256 + ks + kq * 4];
        }
    };
    auto STOREI = [&](int buf) {
        in_s[buf][kq * 4 + 0][bb] = inr.x;
        in_s[buf][kq * 4 + 1][bb] = inr.y;
        in_s[buf][kq * 4 + 2][bb] = inr.z;
        in_s[buf][kq * 4 + 3][bb] = inr.w;
    };

    CPW(0, 0);
    CPW(1, 1);
    LOADI(0);
    STOREI(0);

    int bw = 0;
    for (int kc = 0; kc < 16; ++kc) {
        if (kc < 15) CP_WAIT1(); else CP_WAIT0();
        __syncthreads();

        if (kc < 14) {
            int bw2 = bw + 2; if (bw2 >= 3) bw2 -= 3;
            CPW(kc + 2, bw2);
        }
        if (kc < 15) LOADI(kc + 1);

        const int bufi = kc & 1;
#pragma unroll 8
        for (int kl = 0; kl < 32; ++kl) {
            unsigned long long a01 = *(const unsigned long long*)&in_s[bufi][kl][ty * 2];
            float4 w = *(const float4*)&w_s[bw][kl][tx * 4];
            unsigned long long wx = pk2(w.x, w.x);
            unsigned long long wy = pk2(w.y, w.y);
            unsigned long long wz = pk2(w.z, w.z);
            unsigned long long ww = pk2(w.w, w.w);
            fma2(acc[0], a01, wx); fma2(acc[1], a01, wy);
            fma2(acc[2], a01, wz); fma2(acc[3], a01, ww);
        }
        if (kc < 15) STOREI((kc + 1) & 1);
        bw = (bw == 2) ? 0 : bw + 1;
    }

    // epilogue: + x*Win, tanh, store
    const int cell = (i * 64 + j) * 64;
    float4 wv = *(const float4*)&Win[n0 + tx * 4];
    const int bA = b0 + ty * 2;
    const int bB = bA + 1;
    const float xA = x[(bA * 64 + i) * 64 + j];
    const float xB = x[(bB * 64 + i) * 64 + j];

    float lo0, hi0, lo1, hi1, lo2, hi2, lo3, hi3;
    unpk2(acc[0], lo0, hi0);
    unpk2(acc[1], lo1, hi1);
    unpk2(acc[2], lo2, hi2);
    unpk2(acc[3], lo3, hi3);

    float4 oA, oB;
    oA.x = tanhf(lo0 + xA * wv.x); oA.y = tanhf(lo1 + xA * wv.y);
    oA.z = tanhf(lo2 + xA * wv.z); oA.w = tanhf(lo3 + xA * wv.w);
    oB.x = tanhf(hi0 + xB * wv.x); oB.y = tanhf(hi1 + xB * wv.y);
    oB.z = tanhf(hi2 + xB * wv.z); oB.w = tanhf(hi3 + xB * wv.w);

    *(float4*)&g_state[(cell + bA) * 256 + n0 + tx * 4] = oA;
    *(float4*)&g_state[(cell + bB) * 256 + n0 + tx * 4] = oB;
}

// ---------------------------------------------------------------------------
// Phase 2a: HtH = 64x64 tiles, 45 pairs, cp.async 3-buffer pipeline (R14 —
// the proven win) upgraded from cp4 to cp16 staging: 2 cp16/thread/matrix
// per chunk, 16B transactions, zfill for l >= 3969.  Compute loop and output
// identical to R2/R14 -> values bitwise identical.
// ---------------------------------------------------------------------------
#define HTH_SMEM (3 * 2 * 32 * 64 * 4)   // 49152

__global__ __launch_bounds__(256) void hth_kernel()
{
    extern __shared__ float hsm[];
    float (*Hd)[32][64] = (float(*)[32][64])hsm;                 // [3][32][64]
    float (*He)[32][64] = (float(*)[32][64])(hsm + 3 * 32 * 64); // [3][32][64]

    int rem = (int)blockIdx.x;
    int ti = 0;
    while (rem >= 9 - ti) { rem -= 9 - ti; ++ti; }
    const int tj = ti + rem;
    const int b = (int)blockIdx.y;
    const int d0 = ti * 64, e0 = tj * 64;
    const bool dLeft = d0 < 256, dOnes = d0 >= 512;
    const bool eLeft = e0 < 256, eOnes = e0 >= 512;
    const int dColn = dLeft ? d0 : d0 - 256;
    const int eColn = eLeft ? e0 : e0 - 256;

    const int tid = (int)threadIdx.x;
    const int tx = tid & 15, ty = tid >> 4;

    const unsigned int hd_base = smem_u32(&Hd[0][0][0]);
    const unsigned int he_base = smem_u32(&He[0][0][0]);

    auto STAGE = [&](int l0, int buf) {
        const unsigned int db = hd_base + (unsigned int)buf * (32 * 64 * 4);
        const unsigned int eb = he_base + (unsigned int)buf * (32 * 64 * 4);
#pragma unroll
        for (int t = 0; t < 2; ++t) {
            const int idx = tid + t * 256;   // 0..511
            const int kk = idx >> 4;         // 0..31
            const int q  = idx & 15;         // dd quad: dd = q*4..+3
            const int l = l0 + kk;
            const bool valid = (l < 3969);
            const int lc = valid ? l : 0;
            const int r = lc / 63;
            const int c = lc - r * 63;
            const int sz = valid ? 16 : 0;
            const unsigned int off = (unsigned int)(kk * 64 + q * 4) * 4;
            if (dOnes) {
                float4 v = make_float4((valid && q == 0) ? 1.f : 0.f, 0.f, 0.f, 0.f);
                *(float4*)&Hd[buf][kk][q * 4] = v;
            } else {
                int cellD = dLeft ? ((r + 1) * 64 + c) : (r * 64 + c + 1);
                cp16z(db + off, &g_state[(cellD * 64 + b) * 256 + dColn + q * 4], sz);
            }
            if (eOnes) {
                float4 v = make_float4((valid && q == 0) ? 1.f : 0.f, 0.f, 0.f, 0.f);
                *(float4*)&He[buf][kk][q * 4] = v;
            } else {
                int cellE = eLeft ? ((r + 1) * 64 + c) : (r * 64 + c + 1);
                cp16z(eb + off, &g_state[(cellE * 64 + b) * 256 + eColn + q * 4], sz);
            }
        }
        CP_COMMIT();
    };

    unsigned long long acc[2][4];
#pragma unroll
    for (int p = 0; p < 2; ++p)
#pragma unroll
        for (int c = 0; c < 4; ++c) acc[p][c] = 0ull;

    STAGE(0, 0);
    STAGE(32, 1);

    int bw = 0;
    for (int ch = 0; ch < 125; ++ch) {
        if (ch < 124) CP_WAIT1(); else CP_WAIT0();
        __syncthreads();

        if (ch < 123) {
            int bw2 = bw + 2; if (bw2 >= 3) bw2 -= 3;
            STAGE((ch + 2) * 32, bw2);
        }

#pragma unroll 8
        for (int kk = 0; kk < 32; ++kk) {
            unsigned long long a01 = *(const unsigned long long*)&Hd[bw][kk][ty * 4];
            unsigned long long a23 = *(const unsigned long long*)&Hd[bw][kk][ty * 4 + 2];
            float4 w = *(const float4*)&He[bw][kk][tx * 4];
            unsigned long long wx = pk2(w.x, w.x);
            unsigned long long wy = pk2(w.y, w.y);
            unsigned long long wz = pk2(w.z, w.z);
            unsigned long long ww = pk2(w.w, w.w);
            fma2(acc[0][0], a01, wx); fma2(acc[0][1], a01, wy);
            fma2(acc[0][2], a01, wz); fma2(acc[0][3], a01, ww);
            fma2(acc[1][0], a23, wx); fma2(acc[1][1], a23, wy);
            fma2(acc[1][2], a23, wz); fma2(acc[1][3], a23, ww);
        }
        bw = (bw == 2) ? 0 : bw + 1;
    }

    float v[4][4];
#pragma unroll
    for (int p = 0; p < 2; ++p)
#pragma unroll
        for (int c = 0; c < 4; ++c)
            unpk2(acc[p][c], v[2 * p][c], v[2 * p + 1][c]);

    float* __restrict__ A = g_A + b * 513 * 520;
#pragma unroll
    for (int r = 0; r < 4; ++r) {
        int dr = d0 + ty * 4 + r;
        if (dr >= 513) continue;
#pragma unroll
        for (int c = 0; c < 4; ++c) {
            int e = e0 + tx * 4 + c;
            if (e >= 513) continue;
            float val = v[r][c];
            if (dr == e) val += 25.0f;
            A[dr * 520 + e] = val;
            if (ti != tj) A[e * 520 + dr] = val;
        }
    }
}

// ---------------------------------------------------------------------------
// Phase 2b: HtU -> column 513 of A.  VERBATIM (sequential (r,c) numerics —
// do NOT reassociate; R4 lesson).
// ---------------------------------------------------------------------------
__global__ __launch_bounds__(256) void htu_kernel(const float* __restrict__ x)
{
    const int b = (int)blockIdx.x;
    const int dcol = (int)blockIdx.y * 256 + (int)threadIdx.x;
    if (dcol >= 513) return;
    const float* __restrict__ xb = x + b * 4096;
    float acc = 0.f;
    if (dcol < 256) {
        for (int r = 0; r < 63; ++r)
            for (int c = 0; c < 63; ++c)
                acc += xb[(r + 1) * 64 + c + 1] *
                       g_state[(((r + 1) * 64 + c) * 64 + b) * 256 + dcol];
    } else if (dcol < 512) {
        const int d2 = dcol - 256;
        for (int r = 0; r < 63; ++r)
            for (int c = 0; c < 63; ++c)
                acc += xb[(r + 1) * 64 + c + 1] *
                       g_state[((r * 64 + (c + 1)) * 64 + b) * 256 + d2];
    } else {
        for (int r = 0; r < 63; ++r)
            for (int c = 0; c < 63; ++c)
                acc += xb[(r + 1) * 64 + c + 1];
    }
    g_A[(b * 513 + dcol) * 520 + 513] = acc;
}

// ---------------------------------------------------------------------------
// Phase 3: per-batch blocked LU (no pivoting; SPD) + back substitution.
// VERBATIM from the passing builds.
// ---------------------------------------------------------------------------
__global__ __launch_bounds__(512) void solve_kernel(float* __restrict__ out)
{
    __shared__ float P[513 * 17];
    __shared__ __align__(16) float Us[16 * 132];
    __shared__ float red[16];

    const int b = (int)blockIdx.x;
    const int tid = (int)threadIdx.x;
    float* __restrict__ A = g_A + b * 513 * 520;

    for (int k0 = 0; k0 < 513; k0 += 16) {
        const int nb = (513 - k0) < 16 ? (513 - k0) : 16;
        const int nrows = 513 - k0;

        for (int idx = tid; idx < nrows * nb; idx += 512) {
            int rr = idx / nb, cc = idx - rr * nb;
            P[rr * 17 + cc] = A[(k0 + rr) * 520 + (k0 + cc)];
        }
        __syncthreads();

        for (int kk = 0; kk < nb; ++kk) {
            float inv = 1.0f / P[kk * 17 + kk];
            for (int rr = kk + 1 + tid; rr < nrows; rr += 512) {
                float lv = P[rr * 17 + kk] * inv;
                P[rr * 17 + kk] = lv;
                for (int cc = kk + 1; cc < nb; ++cc)
                    P[rr * 17 + cc] -= lv * P[kk * 17 + cc];
            }
            __syncthreads();
        }

        for (int idx = tid; idx < nrows * nb; idx += 512) {
            int rr = idx / nb, cc = idx - rr * nb;
            A[(k0 + rr) * 520 + (k0 + cc)] = P[rr * 17 + cc];
        }
        __syncthreads();

        const int cstart = k0 + nb;
        const int width = 514 - cstart;
        for (int ch = 0; ch < width; ch += 128) {
            int wlen = width - ch; if (wlen > 128) wlen = 128;
            const int wlenp = (wlen + 3) & ~3;
            const int cbase = cstart + ch;

            for (int idx = tid; idx < nb * wlenp; idx += 512) {
                int rr = idx / wlenp, cc = idx - rr * wlenp;
                Us[rr * 132 + cc] = A[(k0 + rr) * 520 + cbase + cc];
            }
            __syncthreads();

            for (int cc = tid; cc < wlenp; cc += 512) {
                float col[16];
                for (int m = 0; m < nb; ++m) col[m] = Us[m * 132 + cc];
                for (int kk = 1; kk < nb; ++kk) {
                    float v = col[kk];
                    for (int m = 0; m < kk; ++m) v -= P[kk * 17 + m] * col[m];
                    col[kk] = v;
                }
                for (int m = 0; m < nb; ++m) {
                    Us[m * 132 + cc] = col[m];
                    A[(k0 + m) * 520 + cbase + cc] = col[m];
                }
            }
            __syncthreads();

            const int trows = nrows - nb;
            const int npr = (trows + 1) >> 1;
            const int ncq = wlenp >> 2;
            for (int idx = tid; idx < npr * ncq; idx += 512) {
                int pr = idx / ncq, cq = idx - pr * ncq;
                int row0 = cstart + pr * 2;
                int cc = cq * 4;
                bool has2 = (pr * 2 + 1) < trows;
                const unsigned long long* pa0 =
                    (const unsigned long long*)&A[row0 * 520 + cbase + cc];
                const unsigned long long* pa1 =
                    (const unsigned long long*)&A[(row0 + 1) * 520 + cbase + cc];
                unsigned long long a00 = pa0[0], a01v = pa0[1];
                unsigned long long a10 = has2 ? pa1[0] : a00;
                unsigned long long a11 = has2 ? pa1[1] : a01v;
                const float* P0 = &P[(row0 - k0) * 17];
                const float* P1 = has2 ? (P0 + 17) : P0;
#pragma unroll
                for (int m = 0; m < 16; ++m) {
                    if (m < nb) {
                        const unsigned long long* pu =
                            (const unsigned long long*)&Us[m * 132 + cc];
                        unsigned long long u01 = pu[0], u23 = pu[1];
                        float p0 = P0[m], p1 = P1[m];
                        unsigned long long np0 = pk2(-p0, -p0);
                        unsigned long long np1 = pk2(-p1, -p1);
                        fma2(a00, u01, np0); fma2(a01v, u23, np0);
                        fma2(a10, u01, np1); fma2(a11, u23, np1);
                    }
                }
                unsigned long long* sa0 =
                    (unsigned long long*)&A[row0 * 520 + cbase + cc];
                sa0[0] = a00; sa0[1] = a01v;
                if (has2) {
                    unsigned long long* sa1 =
                        (unsigned long long*)&A[(row0 + 1) * 520 + cbase + cc];
                    sa1[0] = a10; sa1[1] = a11;
                }
            }
            __syncthreads();
        }
    }

    float* xs = P;
    const int lane = tid & 31, wid = tid >> 5;
    for (int r = 512; r >= 0; --r) {
        float part = 0.f;
        for (int c = r + 1 + tid; c <= 512; c += 512)
            part += A[r * 520 + c] * xs[c];
#pragma unroll
        for (int off = 16; off > 0; off >>= 1)
            part += __shfl_down_sync(0xffffffffu, part, off);
        if (lane == 0) red[wid] = part;
        __syncthreads();
        if (tid == 0) {
            float s = 0.f;
#pragma unroll
            for (int w2 = 0; w2 < 16; ++w2) s += red[w2];
            xs[r] = (A[r * 520 + 513] - s) / A[r * 520 + r];
        }
        __syncthreads();
    }
    for (int i2 = tid; i2 < 513; i2 += 512)
        out[b * 513 + i2] = xs[i2];
}

// ---------------------------------------------------------------------------
extern "C" void kernel_launch(void* const* d_in, const int* in_sizes, int n_in,
                              void* d_out, int out_size)
{
    const float* x   = (const float*)d_in[0];
    const float* Win = (const float*)d_in[1];
    const float* W1  = (const float*)d_in[2];
    const float* W2  = (const float*)d_in[3];
    float* out = (float*)d_out;

    static bool attr_set = false;
    if (!attr_set) {
        cudaFuncSetAttribute(scan_diag,
                             cudaFuncAttributeMaxDynamicSharedMemorySize, SCAN_SMEM);
        cudaFuncSetAttribute(hth_kernel,
                             cudaFuncAttributeMaxDynamicSharedMemorySize, HTH_SMEM);
        attr_set = true;
    }

    for (int d = 0; d < 127; ++d) {
        int i_min = d > 63 ? d - 63 : 0;
        int i_max = d < 63 ? d : 63;
        dim3 grid(i_max - i_min + 1, 2, 4);
        scan_diag<<<grid, 256, SCAN_SMEM>>>(x, Win, W1, W2, d, i_min);
    }
    hth_kernel<<<dim3(45, 64), 256, HTH_SMEM>>>();
    htu_kernel<<<dim3(64, 3), 256>>>(x);
    solve_kernel<<<64, 512>>>(out);
}

// round 16
// speedup vs baseline: 1.4850x; 1.0278x over previous
#include <cuda_runtime.h>

// Problem constants: B=64, H=64, W=64, n=256, NF=513, L=63*63=3969, alpha^2=25

__device__ float g_state[64 * 64 * 64 * 256];   // [cell=(i*64+j)][b][n]
__device__ float g_A[64 * 513 * 520];           // augmented [513 x 514] per batch, ld=520

// ---- packed f32x2 helpers (dual fp32 pipe) ---------------------------------
__device__ __forceinline__ unsigned long long pk2(float a, float b) {
    unsigned long long r;
    asm("mov.b64 %0,{%1,%2};" : "=l"(r) : "f"(a), "f"(b));
    return r;
}
__device__ __forceinline__ void fma2(unsigned long long& d,
                                     unsigned long long a, unsigned long long b) {
    asm("fma.rn.f32x2 %0,%1,%2,%0;" : "+l"(d) : "l"(a), "l"(b));
}
__device__ __forceinline__ void unpk2(unsigned long long v, float& a, float& b) {
    asm("mov.b64 {%0,%1},%2;" : "=f"(a), "=f"(b) : "l"(v));
}

// ---- cp.async helpers -------------------------------------------------------
__device__ __forceinline__ void cp16(unsigned int dst, const void* src) {
    asm volatile("cp.async.cg.shared.global [%0], [%1], 16;"
                 :: "r"(dst), "l"(src) : "memory");
}
__device__ __forceinline__ void cp16z(unsigned int dst, const void* src, int srcsize) {
    asm volatile("cp.async.cg.shared.global [%0], [%1], 16, %2;"
                 :: "r"(dst), "l"(src), "r"(srcsize) : "memory");
}
#define CP_COMMIT() asm volatile("cp.async.commit_group;" ::: "memory")
#define CP_WAIT1()  asm volatile("cp.async.wait_group 1;" ::: "memory")
#define CP_WAIT0()  asm volatile("cp.async.wait_group 0;" ::: "memory")

__device__ __forceinline__ unsigned int smem_u32(const void* p) {
    return (unsigned int)__cvta_generic_to_shared(p);
}

// ---------------------------------------------------------------------------
// Phase 1: wavefront scan, one launch per anti-diagonal.
// grid = (cells, 2 batch-halves, 4 n-quarters), 256 threads,
// tile 32 batches x 64 features, K-CHUNK 64 (8 chunks -> half the per-cell
// barrier/wait stages of R15).  W staged by cp16 (3 buffers, depth-2);
// input via register path (2 float4/thread), double-buffered.
// Per-output k order ascending 0..511, one accumulator -> bitwise == R15.
// ---------------------------------------------------------------------------
#define SCAN_SMEM ((3 * 64 * 64 + 2 * 64 * 34) * 4)   // 49152 + 17408 = 66560

__global__ __launch_bounds__(256) void scan_diag(
    const float* __restrict__ x, const float* __restrict__ Win,
    const float* __restrict__ W1, const float* __restrict__ W2,
    int d, int i_min)
{
    extern __shared__ float sm[];
    float (*w_s)[64][64]  = (float(*)[64][64])sm;                 // [3][64][64]
    float (*in_s)[64][34] = (float(*)[64][34])(sm + 3 * 64 * 64); // [2][64][34]

    const int i = i_min + (int)blockIdx.x;
    const int j = d - i;
    const int b0 = (int)blockIdx.y * 32;
    const int n0 = (int)blockIdx.z * 64;
    const int tid = (int)threadIdx.x;
    const int tx = tid & 15;    // n: 4 cols at n0 + tx*4
    const int ty = tid >> 4;    // batch pair: b0 + ty*2, +1

    const bool hasL = (j > 0);
    const bool hasU = (i > 0);
    const int cellL = hasL ? ((i * 64 + (j - 1)) * 64) : 0;
    const int cellU = hasU ? (((i - 1) * 64 + j) * 64) : 0;

    const int bb = tid >> 3;   // 0..31 batch for input staging
    const int kq = tid & 7;    // 0..7  k-quad for input staging (x2 halves)

    const unsigned int w_base = smem_u32(&w_s[0][0][0]);

    unsigned long long acc[4];
    acc[0] = acc[1] = acc[2] = acc[3] = 0ull;

    float4 inr[2];

    auto CPW = [&](int kc, int buf) {
        const int k0 = kc * 64;
        const float* __restrict__ Wm = (k0 < 256) ? W1 : W2;
        const int ks = (k0 < 256) ? k0 : (k0 - 256);
        const unsigned int base = w_base + (unsigned int)buf * (64 * 64 * 4);
#pragma unroll
        for (int t = 0; t < 4; ++t) {
            int idx = tid + t * 256;       // 0..1023
            int kl = idx >> 4;             // 0..63
            int q  = idx & 15;             // 0..15
            cp16(base + (unsigned int)(kl * 64 + q * 4) * 4,
                 &Wm[(ks + kl) * 256 + n0 + q * 4]);
        }
        CP_COMMIT();
    };
    auto LOADI = [&](int kc) {
        const int k0 = kc * 64;
        const bool isLeft = (k0 < 256);
        const bool has = isLeft ? hasL : hasU;
        const int ks = isLeft ? k0 : (k0 - 256);
        const int cell = isLeft ? cellL : cellU;
#pragma unroll
        for (int h = 0; h < 2; ++h) {
            inr[h] = make_float4(0.f, 0.f, 0.f, 0.f);
            if (has)
                inr[h] = *(const float4*)
                    &g_state[(cell + b0 + bb) * 256 + ks + kq * 4 + h * 32];
        }
    };
    auto STOREI = [&](int buf) {
#pragma unroll
        for (int h = 0; h < 2; ++h) {
            const int kr = kq * 4 + h * 32;
            in_s[buf][kr + 0][bb] = inr[h].x;
            in_s[buf][kr + 1][bb] = inr[h].y;
            in_s[buf][kr + 2][bb] = inr[h].z;
            in_s[buf][kr + 3][bb] = inr[h].w;
        }
    };

    CPW(0, 0);
    CPW(1, 1);
    LOADI(0);
    STOREI(0);

    int bw = 0;
    for (int kc = 0; kc < 8; ++kc) {
        if (kc < 7) CP_WAIT1(); else CP_WAIT0();
        __syncthreads();

        if (kc < 6) {
            int bw2 = bw + 2; if (bw2 >= 3) bw2 -= 3;
            CPW(kc + 2, bw2);
        }
        if (kc < 7) LOADI(kc + 1);

        const int bufi = kc & 1;
#pragma unroll 8
        for (int kl = 0; kl < 64; ++kl) {
            unsigned long long a01 = *(const unsigned long long*)&in_s[bufi][kl][ty * 2];
            float4 w = *(const float4*)&w_s[bw][kl][tx * 4];
            unsigned long long wx = pk2(w.x, w.x);
            unsigned long long wy = pk2(w.y, w.y);
            unsigned long long wz = pk2(w.z, w.z);
            unsigned long long ww = pk2(w.w, w.w);
            fma2(acc[0], a01, wx); fma2(acc[1], a01, wy);
            fma2(acc[2], a01, wz); fma2(acc[3], a01, ww);
        }
        if (kc < 7) STOREI((kc + 1) & 1);
        bw = (bw == 2) ? 0 : bw + 1;
    }

    // epilogue: + x*Win, tanh, store
    const int cell = (i * 64 + j) * 64;
    float4 wv = *(const float4*)&Win[n0 + tx * 4];
    const int bA = b0 + ty * 2;
    const int bB = bA + 1;
    const float xA = x[(bA * 64 + i) * 64 + j];
    const float xB = x[(bB * 64 + i) * 64 + j];

    float lo0, hi0, lo1, hi1, lo2, hi2, lo3, hi3;
    unpk2(acc[0], lo0, hi0);
    unpk2(acc[1], lo1, hi1);
    unpk2(acc[2], lo2, hi2);
    unpk2(acc[3], lo3, hi3);

    float4 oA, oB;
    oA.x = tanhf(lo0 + xA * wv.x); oA.y = tanhf(lo1 + xA * wv.y);
    oA.z = tanhf(lo2 + xA * wv.z); oA.w = tanhf(lo3 + xA * wv.w);
    oB.x = tanhf(hi0 + xB * wv.x); oB.y = tanhf(hi1 + xB * wv.y);
    oB.z = tanhf(hi2 + xB * wv.z); oB.w = tanhf(hi3 + xB * wv.w);

    *(float4*)&g_state[(cell + bA) * 256 + n0 + tx * 4] = oA;
    *(float4*)&g_state[(cell + bB) * 256 + n0 + tx * 4] = oB;
}

// ---------------------------------------------------------------------------
// Phase 2a: HtH = 64x64 tiles, 45 pairs, cp16 3-buffer pipeline.
// VERBATIM from the 8400us build.
// ---------------------------------------------------------------------------
#define HTH_SMEM (3 * 2 * 32 * 64 * 4)   // 49152

__global__ __launch_bounds__(256) void hth_kernel()
{
    extern __shared__ float hsm[];
    float (*Hd)[32][64] = (float(*)[32][64])hsm;                 // [3][32][64]
    float (*He)[32][64] = (float(*)[32][64])(hsm + 3 * 32 * 64); // [3][32][64]

    int rem = (int)blockIdx.x;
    int ti = 0;
    while (rem >= 9 - ti) { rem -= 9 - ti; ++ti; }
    const int tj = ti + rem;
    const int b = (int)blockIdx.y;
    const int d0 = ti * 64, e0 = tj * 64;
    const bool dLeft = d0 < 256, dOnes = d0 >= 512;
    const bool eLeft = e0 < 256, eOnes = e0 >= 512;
    const int dColn = dLeft ? d0 : d0 - 256;
    const int eColn = eLeft ? e0 : e0 - 256;

    const int tid = (int)threadIdx.x;
    const int tx = tid & 15, ty = tid >> 4;

    const unsigned int hd_base = smem_u32(&Hd[0][0][0]);
    const unsigned int he_base = smem_u32(&He[0][0][0]);

    auto STAGE = [&](int l0, int buf) {
        const unsigned int db = hd_base + (unsigned int)buf * (32 * 64 * 4);
        const unsigned int eb = he_base + (unsigned int)buf * (32 * 64 * 4);
#pragma unroll
        for (int t = 0; t < 2; ++t) {
            const int idx = tid + t * 256;   // 0..511
            const int kk = idx >> 4;         // 0..31
            const int q  = idx & 15;         // dd quad: dd = q*4..+3
            const int l = l0 + kk;
            const bool valid = (l < 3969);
            const int lc = valid ? l : 0;
            const int r = lc / 63;
            const int c = lc - r * 63;
            const int sz = valid ? 16 : 0;
            const unsigned int off = (unsigned int)(kk * 64 + q * 4) * 4;
            if (dOnes) {
                float4 v = make_float4((valid && q == 0) ? 1.f : 0.f, 0.f, 0.f, 0.f);
                *(float4*)&Hd[buf][kk][q * 4] = v;
            } else {
                int cellD = dLeft ? ((r + 1) * 64 + c) : (r * 64 + c + 1);
                cp16z(db + off, &g_state[(cellD * 64 + b) * 256 + dColn + q * 4], sz);
            }
            if (eOnes) {
                float4 v = make_float4((valid && q == 0) ? 1.f : 0.f, 0.f, 0.f, 0.f);
                *(float4*)&He[buf][kk][q * 4] = v;
            } else {
                int cellE = eLeft ? ((r + 1) * 64 + c) : (r * 64 + c + 1);
                cp16z(eb + off, &g_state[(cellE * 64 + b) * 256 + eColn + q * 4], sz);
            }
        }
        CP_COMMIT();
    };

    unsigned long long acc[2][4];
#pragma unroll
    for (int p = 0; p < 2; ++p)
#pragma unroll
        for (int c = 0; c < 4; ++c) acc[p][c] = 0ull;

    STAGE(0, 0);
    STAGE(32, 1);

    int bw = 0;
    for (int ch = 0; ch < 125; ++ch) {
        if (ch < 124) CP_WAIT1(); else CP_WAIT0();
        __syncthreads();

        if (ch < 123) {
            int bw2 = bw + 2; if (bw2 >= 3) bw2 -= 3;
            STAGE((ch + 2) * 32, bw2);
        }

#pragma unroll 8
        for (int kk = 0; kk < 32; ++kk) {
            unsigned long long a01 = *(const unsigned long long*)&Hd[bw][kk][ty * 4];
            unsigned long long a23 = *(const unsigned long long*)&Hd[bw][kk][ty * 4 + 2];
            float4 w = *(const float4*)&He[bw][kk][tx * 4];
            unsigned long long wx = pk2(w.x, w.x);
            unsigned long long wy = pk2(w.y, w.y);
            unsigned long long wz = pk2(w.z, w.z);
            unsigned long long ww = pk2(w.w, w.w);
            fma2(acc[0][0], a01, wx); fma2(acc[0][1], a01, wy);
            fma2(acc[0][2], a01, wz); fma2(acc[0][3], a01, ww);
            fma2(acc[1][0], a23, wx); fma2(acc[1][1], a23, wy);
            fma2(acc[1][2], a23, wz); fma2(acc[1][3], a23, ww);
        }
        bw = (bw == 2) ? 0 : bw + 1;
    }

    float v[4][4];
#pragma unroll
    for (int p = 0; p < 2; ++p)
#pragma unroll
        for (int c = 0; c < 4; ++c)
            unpk2(acc[p][c], v[2 * p][c], v[2 * p + 1][c]);

    float* __restrict__ A = g_A + b * 513 * 520;
#pragma unroll
    for (int r = 0; r < 4; ++r) {
        int dr = d0 + ty * 4 + r;
        if (dr >= 513) continue;
#pragma unroll
        for (int c = 0; c < 4; ++c) {
            int e = e0 + tx * 4 + c;
            if (e >= 513) continue;
            float val = v[r][c];
            if (dr == e) val += 25.0f;
            A[dr * 520 + e] = val;
            if (ti != tj) A[e * 520 + dr] = val;
        }
    }
}

// ---------------------------------------------------------------------------
// Phase 2b: HtU -> column 513 of A.  VERBATIM (sequential (r,c) numerics —
// do NOT reassociate; R4 lesson).
// ---------------------------------------------------------------------------
__global__ __launch_bounds__(256) void htu_kernel(const float* __restrict__ x)
{
    const int b = (int)blockIdx.x;
    const int dcol = (int)blockIdx.y * 256 + (int)threadIdx.x;
    if (dcol >= 513) return;
    const float* __restrict__ xb = x + b * 4096;
    float acc = 0.f;
    if (dcol < 256) {
        for (int r = 0; r < 63; ++r)
            for (int c = 0; c < 63; ++c)
                acc += xb[(r + 1) * 64 + c + 1] *
                       g_state[(((r + 1) * 64 + c) * 64 + b) * 256 + dcol];
    } else if (dcol < 512) {
        const int d2 = dcol - 256;
        for (int r = 0; r < 63; ++r)
            for (int c = 0; c < 63; ++c)
                acc += xb[(r + 1) * 64 + c + 1] *
                       g_state[((r * 64 + (c + 1)) * 64 + b) * 256 + d2];
    } else {
        for (int r = 0; r < 63; ++r)
            for (int c = 0; c < 63; ++c)
                acc += xb[(r + 1) * 64 + c + 1];
    }
    g_A[(b * 513 + dcol) * 520 + 513] = acc;
}

// ---------------------------------------------------------------------------
// Phase 3: per-batch blocked LU (no pivoting; SPD) + back substitution.
// VERBATIM from the passing builds.
// ---------------------------------------------------------------------------
__global__ __launch_bounds__(512) void solve_kernel(float* __restrict__ out)
{
    __shared__ float P[513 * 17];
    __shared__ __align__(16) float Us[16 * 132];
    __shared__ float red[16];

    const int b = (int)blockIdx.x;
    const int tid = (int)threadIdx.x;
    float* __restrict__ A = g_A + b * 513 * 520;

    for (int k0 = 0; k0 < 513; k0 += 16) {
        const int nb = (513 - k0) < 16 ? (513 - k0) : 16;
        const int nrows = 513 - k0;

        for (int idx = tid; idx < nrows * nb; idx += 512) {
            int rr = idx / nb, cc = idx - rr * nb;
            P[rr * 17 + cc] = A[(k0 + rr) * 520 + (k0 + cc)];
        }
        __syncthreads();

        for (int kk = 0; kk < nb; ++kk) {
            float inv = 1.0f / P[kk * 17 + kk];
            for (int rr = kk + 1 + tid; rr < nrows; rr += 512) {
                float lv = P[rr * 17 + kk] * inv;
                P[rr * 17 + kk] = lv;
                for (int cc = kk + 1; cc < nb; ++cc)
                    P[rr * 17 + cc] -= lv * P[kk * 17 + cc];
            }
            __syncthreads();
        }

        for (int idx = tid; idx < nrows * nb; idx += 512) {
            int rr = idx / nb, cc = idx - rr * nb;
            A[(k0 + rr) * 520 + (k0 + cc)] = P[rr * 17 + cc];
        }
        __syncthreads();

        const int cstart = k0 + nb;
        const int width = 514 - cstart;
        for (int ch = 0; ch < width; ch += 128) {
            int wlen = width - ch; if (wlen > 128) wlen = 128;
            const int wlenp = (wlen + 3) & ~3;
            const int cbase = cstart + ch;

            for (int idx = tid; idx < nb * wlenp; idx += 512) {
                int rr = idx / wlenp, cc = idx - rr * wlenp;
                Us[rr * 132 + cc] = A[(k0 + rr) * 520 + cbase + cc];
            }
            __syncthreads();

            for (int cc = tid; cc < wlenp; cc += 512) {
                float col[16];
                for (int m = 0; m < nb; ++m) col[m] = Us[m * 132 + cc];
                for (int kk = 1; kk < nb; ++kk) {
                    float v = col[kk];
                    for (int m = 0; m < kk; ++m) v -= P[kk * 17 + m] * col[m];
                    col[kk] = v;
                }
                for (int m = 0; m < nb; ++m) {
                    Us[m * 132 + cc] = col[m];
                    A[(k0 + m) * 520 + cbase + cc] = col[m];
                }
            }
            __syncthreads();

            const int trows = nrows - nb;
            const int npr = (trows + 1) >> 1;
            const int ncq = wlenp >> 2;
            for (int idx = tid; idx < npr * ncq; idx += 512) {
                int pr = idx / ncq, cq = idx - pr * ncq;
                int row0 = cstart + pr * 2;
                int cc = cq * 4;
                bool has2 = (pr * 2 + 1) < trows;
                const unsigned long long* pa0 =
                    (const unsigned long long*)&A[row0 * 520 + cbase + cc];
                const unsigned long long* pa1 =
                    (const unsigned long long*)&A[(row0 + 1) * 520 + cbase + cc];
                unsigned long long a00 = pa0[0], a01v = pa0[1];
                unsigned long long a10 = has2 ? pa1[0] : a00;
                unsigned long long a11 = has2 ? pa1[1] : a01v;
                const float* P0 = &P[(row0 - k0) * 17];
                const float* P1 = has2 ? (P0 + 17) : P0;
#pragma unroll
                for (int m = 0; m < 16; ++m) {
                    if (m < nb) {
                        const unsigned long long* pu =
                            (const unsigned long long*)&Us[m * 132 + cc];
                        unsigned long long u01 = pu[0], u23 = pu[1];
                        float p0 = P0[m], p1 = P1[m];
                        unsigned long long np0 = pk2(-p0, -p0);
                        unsigned long long np1 = pk2(-p1, -p1);
                        fma2(a00, u01, np0); fma2(a01v, u23, np0);
                        fma2(a10, u01, np1); fma2(a11, u23, np1);
                    }
                }
                unsigned long long* sa0 =
                    (unsigned long long*)&A[row0 * 520 + cbase + cc];
                sa0[0] = a00; sa0[1] = a01v;
                if (has2) {
                    unsigned long long* sa1 =
                        (unsigned long long*)&A[(row0 + 1) * 520 + cbase + cc];
                    sa1[0] = a10; sa1[1] = a11;
                }
            }
            __syncthreads();
        }
    }

    float* xs = P;
    const int lane = tid & 31, wid = tid >> 5;
    for (int r = 512; r >= 0; --r) {
        float part = 0.f;
        for (int c = r + 1 + tid; c <= 512; c += 512)
            part += A[r * 520 + c] * xs[c];
#pragma unroll
        for (int off = 16; off > 0; off >>= 1)
            part += __shfl_down_sync(0xffffffffu, part, off);
        if (lane == 0) red[wid] = part;
        __syncthreads();
        if (tid == 0) {
            float s = 0.f;
#pragma unroll
            for (int w2 = 0; w2 < 16; ++w2) s += red[w2];
            xs[r] = (A[r * 520 + 513] - s) / A[r * 520 + r];
        }
        __syncthreads();
    }
    for (int i2 = tid; i2 < 513; i2 += 512)
        out[b * 513 + i2] = xs[i2];
}

// ---------------------------------------------------------------------------
extern "C" void kernel_launch(void* const* d_in, const int* in_sizes, int n_in,
                              void* d_out, int out_size)
{
    const float* x   = (const float*)d_in[0];
    const float* Win = (const float*)d_in[1];
    const float* W1  = (const float*)d_in[2];
    const float* W2  = (const float*)d_in[3];
    float* out = (float*)d_out;

    static bool attr_set = false;
    if (!attr_set) {
        cudaFuncSetAttribute(scan_diag,
                             cudaFuncAttributeMaxDynamicSharedMemorySize, SCAN_SMEM);
        cudaFuncSetAttribute(hth_kernel,
                             cudaFuncAttributeMaxDynamicSharedMemorySize, HTH_SMEM);
        attr_set = true;
    }

    for (int d = 0; d < 127; ++d) {
        int i_min = d > 63 ? d - 63 : 0;
        int i_max = d < 63 ? d : 63;
        dim3 grid(i_max - i_min + 1, 2, 4);
        scan_diag<<<grid, 256, SCAN_SMEM>>>(x, Win, W1, W2, d, i_min);
    }
    hth_kernel<<<dim3(45, 64), 256, HTH_SMEM>>>();
    htu_kernel<<<dim3(64, 3), 256>>>(x);
    solve_kernel<<<64, 512>>>(out);
}